// round 10
// baseline (speedup 1.0000x reference)
#include <cuda_runtime.h>
#include <cuda_bf16.h>
#include <math.h>

#define N_NODES 16384
#define IN_DIM  256
#define HEADS   2
#define OUT_CH  256
#define F_DIM   512
#define E_IN    524288

// ---------------- scratch (device globals) ----------------------------------
__device__ float    g_h   [N_NODES * F_DIM];
__device__ float    g_as  [N_NODES * HEADS];
__device__ float    g_ad  [N_NODES * HEADS];
__device__ int      g_deg [N_NODES];
__device__ int      g_off [N_NODES + 1];
__device__ int      g_csr_src[E_IN];
__device__ float    g_h2  [N_NODES * 128];
__device__ float    g_h3  [N_NODES * 64];
__device__ float    g_h4  [N_NODES * 32];
__device__ float    g_h5  [N_NODES * 4];
__device__ int      g_is64;
__device__ __nv_bfloat16 g_ah [N_NODES * F_DIM];
__device__ __nv_bfloat16 g_al [N_NODES * F_DIM];
__device__ __nv_bfloat16 g_ah2[N_NODES * 256];
__device__ __nv_bfloat16 g_al2[N_NODES * 256];
__device__ __nv_bfloat16 g_wh[512 * 256];
__device__ __nv_bfloat16 g_wl[512 * 256];

#define BUF_H   0
#define BUF_H2  3
#define BUF_H3  4
#define BUF_H4  5
__device__ __forceinline__ float* buf_ptr(int id) {
    switch (id) {
        case BUF_H:   return g_h;
        case BUF_H2:  return g_h2;
        case BUF_H3:  return g_h3;
        default:      return g_h4;
    }
}

// ---------------- helpers ---------------------------------------------------
__device__ __forceinline__ float lrelu(float v) { return v > 0.f ? v : 0.2f * v; }

__device__ __forceinline__ float fast_sqrt(float d2) {
    float r = __uint_as_float(0x5f3759dfu - (__float_as_uint(d2) >> 1));
    float hd = 0.5f * d2;
    r = r * fmaf(-(hd * r), r, 1.5f);
    r = r * fmaf(-(hd * r), r, 1.5f);
    return d2 * r;
}

__device__ __forceinline__ void mma_bf16(float* c, const unsigned* a, const unsigned* b) {
    asm volatile(
        "mma.sync.aligned.m16n8k16.row.col.f32.bf16.bf16.f32 "
        "{%0,%1,%2,%3}, {%4,%5,%6,%7}, {%8,%9}, {%0,%1,%2,%3};"
        : "+f"(c[0]), "+f"(c[1]), "+f"(c[2]), "+f"(c[3])
        : "r"(a[0]), "r"(a[1]), "r"(a[2]), "r"(a[3]), "r"(b[0]), "r"(b[1]));
}

__device__ __forceinline__ void cp_async16(void* smem_dst, const void* gsrc) {
    unsigned s = (unsigned)__cvta_generic_to_shared(smem_dst);
    asm volatile("cp.async.ca.shared.global [%0], [%1], 16;" :: "r"(s), "l"(gsrc));
}
__device__ __forceinline__ void cp_commit() { asm volatile("cp.async.commit_group;"); }
__device__ __forceinline__ void cp_wait0()  { asm volatile("cp.async.wait_group 0;" ::: "memory"); }

__device__ __forceinline__ void split2(float a, float b, __nv_bfloat162& h, __nv_bfloat162& l) {
    __nv_bfloat16 ha = __float2bfloat16_rn(a);
    __nv_bfloat16 hb = __float2bfloat16_rn(b);
    h.x = ha; h.y = hb;
    l.x = __float2bfloat16_rn(a - __bfloat162float(ha));
    l.y = __float2bfloat16_rn(b - __bfloat162float(hb));
}

// ---------------- split fp32 -> bf16 hi/lo (x and weights) -------------------
__global__ void split_kernel(const float* __restrict__ A, int n4, int dest) {
    int i = blockIdx.x * blockDim.x + threadIdx.x;
    if (i >= n4) return;
    float4 v = ((const float4*)A)[i];
    __nv_bfloat162 h0, h1, l0, l1;
    split2(v.x, v.y, h0, l0);
    split2(v.z, v.w, h1, l1);
    __nv_bfloat162* dh = dest ? (__nv_bfloat162*)g_wh : (__nv_bfloat162*)g_ah;
    __nv_bfloat162* dl = dest ? (__nv_bfloat162*)g_wl : (__nv_bfloat162*)g_al;
    dh[i * 2] = h0; dh[i * 2 + 1] = h1;
    dl[i * 2] = l0; dl[i * 2 + 1] = l1;
}

// ---------------- tensor-core GEMM: C = act(A @ W^T + b), split-bf16 ----------
// 128x128 CTA tile, 4 warps, 64x64 warp tile (raises MMA:LDS ratio).
#define SP 24
__global__ __launch_bounds__(128, 2)
void gemm_tc_kernel(const float* __restrict__ bias, int c_id,
                    int Nout, int K, int doRelu, int in_sel, int out_mode) {
    const __nv_bfloat16* Ah = in_sel ? g_ah2 : g_ah;
    const __nv_bfloat16* Al = in_sel ? g_al2 : g_al;
    __shared__ __align__(16) __nv_bfloat16 sAh[2][128 * SP];
    __shared__ __align__(16) __nv_bfloat16 sAl[2][128 * SP];
    __shared__ __align__(16) __nv_bfloat16 sBh[2][128 * SP];
    __shared__ __align__(16) __nv_bfloat16 sBl[2][128 * SP];

    const int tid = threadIdx.x;
    const int m0 = blockIdx.y * 128, n0 = blockIdx.x * 128;
    // loader: thread t owns row t (16 bf16 = two 16B segments)
    const size_t gA = (size_t)(m0 + tid) * K;
    const size_t gB = (size_t)(n0 + tid) * K;
    const int sofs = tid * SP;

    const int w = tid >> 5, lane = tid & 31;
    const int wm = (w & 1) * 64, wn = (w >> 1) * 64;
    const int gr = lane >> 2, tg = lane & 3;

    float acc[4][8][4];
    #pragma unroll
    for (int mt = 0; mt < 4; mt++)
        #pragma unroll
        for (int nt = 0; nt < 8; nt++)
            #pragma unroll
            for (int r = 0; r < 4; r++) acc[mt][nt][r] = 0.f;

    cp_async16(&sAh[0][sofs],     &Ah[gA]);
    cp_async16(&sAh[0][sofs + 8], &Ah[gA + 8]);
    cp_async16(&sAl[0][sofs],     &Al[gA]);
    cp_async16(&sAl[0][sofs + 8], &Al[gA + 8]);
    cp_async16(&sBh[0][sofs],     &g_wh[gB]);
    cp_async16(&sBh[0][sofs + 8], &g_wh[gB + 8]);
    cp_async16(&sBl[0][sofs],     &g_wl[gB]);
    cp_async16(&sBl[0][sofs + 8], &g_wl[gB + 8]);
    cp_commit(); cp_wait0();
    __syncthreads();

    const int T = K >> 4;
    for (int t = 0; t < T; t++) {
        const int cur = t & 1;
        if (t + 1 < T) {
            const int nxt = cur ^ 1;
            int kt = (t + 1) << 4;
            cp_async16(&sAh[nxt][sofs],     &Ah[gA + kt]);
            cp_async16(&sAh[nxt][sofs + 8], &Ah[gA + kt + 8]);
            cp_async16(&sAl[nxt][sofs],     &Al[gA + kt]);
            cp_async16(&sAl[nxt][sofs + 8], &Al[gA + kt + 8]);
            cp_async16(&sBh[nxt][sofs],     &g_wh[gB + kt]);
            cp_async16(&sBh[nxt][sofs + 8], &g_wh[gB + kt + 8]);
            cp_async16(&sBl[nxt][sofs],     &g_wl[gB + kt]);
            cp_async16(&sBl[nxt][sofs + 8], &g_wl[gB + kt + 8]);
            cp_commit();
        }

        unsigned ah[4][4], al[4][4], bh[8][2], bl[8][2];
        #pragma unroll
        for (int mt = 0; mt < 4; mt++) {
            int r = wm + mt * 16 + gr;
            ah[mt][0] = *(const unsigned*)&sAh[cur][r * SP + 2 * tg];
            ah[mt][1] = *(const unsigned*)&sAh[cur][(r + 8) * SP + 2 * tg];
            ah[mt][2] = *(const unsigned*)&sAh[cur][r * SP + 8 + 2 * tg];
            ah[mt][3] = *(const unsigned*)&sAh[cur][(r + 8) * SP + 8 + 2 * tg];
            al[mt][0] = *(const unsigned*)&sAl[cur][r * SP + 2 * tg];
            al[mt][1] = *(const unsigned*)&sAl[cur][(r + 8) * SP + 2 * tg];
            al[mt][2] = *(const unsigned*)&sAl[cur][r * SP + 8 + 2 * tg];
            al[mt][3] = *(const unsigned*)&sAl[cur][(r + 8) * SP + 8 + 2 * tg];
        }
        #pragma unroll
        for (int nt = 0; nt < 8; nt++) {
            int cn = wn + nt * 8 + gr;
            bh[nt][0] = *(const unsigned*)&sBh[cur][cn * SP + 2 * tg];
            bh[nt][1] = *(const unsigned*)&sBh[cur][cn * SP + 8 + 2 * tg];
            bl[nt][0] = *(const unsigned*)&sBl[cur][cn * SP + 2 * tg];
            bl[nt][1] = *(const unsigned*)&sBl[cur][cn * SP + 8 + 2 * tg];
        }
        #pragma unroll
        for (int mt = 0; mt < 4; mt++)
            #pragma unroll
            for (int nt = 0; nt < 8; nt++) {
                mma_bf16(acc[mt][nt], ah[mt], bh[nt]);
                mma_bf16(acc[mt][nt], ah[mt], bl[nt]);
                mma_bf16(acc[mt][nt], al[mt], bh[nt]);
            }

        if (t + 1 < T) cp_wait0();
        __syncthreads();
    }

    // epilogue
    float* C = buf_ptr(c_id);
    #pragma unroll
    for (int mt = 0; mt < 4; mt++) {
        int row = m0 + wm + mt * 16 + gr;
        #pragma unroll
        for (int nt = 0; nt < 8; nt++) {
            int col = n0 + wn + nt * 8 + 2 * tg;
            float b0 = bias ? bias[col] : 0.f;
            float b1 = bias ? bias[col + 1] : 0.f;
            float o0 = acc[mt][nt][0] + b0, o1 = acc[mt][nt][1] + b1;
            float o2 = acc[mt][nt][2] + b0, o3 = acc[mt][nt][3] + b1;
            if (doRelu) {
                o0 = fmaxf(o0, 0.f); o1 = fmaxf(o1, 0.f);
                o2 = fmaxf(o2, 0.f); o3 = fmaxf(o3, 0.f);
            }
            if (out_mode == 0) {
                *(float2*)&C[(size_t)row * Nout + col]       = make_float2(o0, o1);
                *(float2*)&C[(size_t)(row + 8) * Nout + col] = make_float2(o2, o3);
            } else {
                __nv_bfloat162 h0, l0, h1, l1;
                split2(o0, o1, h0, l0);
                split2(o2, o3, h1, l1);
                *(__nv_bfloat162*)&g_ah2[(size_t)row * Nout + col]       = h0;
                *(__nv_bfloat162*)&g_al2[(size_t)row * Nout + col]       = l0;
                *(__nv_bfloat162*)&g_ah2[(size_t)(row + 8) * Nout + col] = h1;
                *(__nv_bfloat162*)&g_al2[(size_t)(row + 8) * Nout + col] = l1;
            }
        }
    }
}

// ---------------- edge_index dtype probe -------------------------------------
__global__ void detect_idx_kernel(const void* __restrict__ ei) {
    if (threadIdx.x == 0 && blockIdx.x == 0) {
        const long long* p = (const long long*)ei;
        int ok64 = 1;
        for (int i = 0; i < 256; i++) {
            long long v = p[i];
            if (v < 0 || v >= N_NODES) { ok64 = 0; break; }
        }
        g_is64 = ok64;
    }
}
__device__ __forceinline__ void edge_nodes(const void* __restrict__ ei, int e,
                                           int& src, int& dst) {
    if (g_is64) {
        const long long* p = (const long long*)ei;
        src = (int)p[e]; dst = (int)p[E_IN + e];
    } else {
        const int* p = (const int*)ei;
        src = p[e]; dst = p[E_IN + e];
    }
    src = min(max(src, 0), N_NODES - 1);
    dst = min(max(dst, 0), N_NODES - 1);
}

// ---------------- CSR build ---------------------------------------------------
__global__ void zero_deg_kernel() {
    int i = blockIdx.x * blockDim.x + threadIdx.x;
    if (i < N_NODES) g_deg[i] = 0;
}
__global__ void hist_kernel(const void* __restrict__ ei) {
    int e = blockIdx.x * blockDim.x + threadIdx.x;
    if (e >= E_IN) return;
    int src, dst; edge_nodes(ei, e, src, dst);
    atomicAdd(&g_deg[dst], 1);
}
__global__ __launch_bounds__(1024)
void scan_kernel() {
    __shared__ int wsum[32];
    int t = threadIdx.x;
    int base = t * 16;
    int4 d0 = *(const int4*)&g_deg[base + 0];
    int4 d1 = *(const int4*)&g_deg[base + 4];
    int4 d2 = *(const int4*)&g_deg[base + 8];
    int4 d3 = *(const int4*)&g_deg[base + 12];
    int v0 = d0.x, v1 = d0.y, v2 = d0.z, v3 = d0.w;
    int v4 = d1.x, v5 = d1.y, v6 = d1.z, v7 = d1.w;
    int v8 = d2.x, v9 = d2.y, v10 = d2.z, v11 = d2.w;
    int v12 = d3.x, v13 = d3.y, v14 = d3.z, v15 = d3.w;
    int l0=0, l1=v0, l2=l1+v1, l3=l2+v2, l4=l3+v3, l5=l4+v4, l6=l5+v5, l7=l6+v6,
        l8=l7+v7, l9=l8+v8, l10=l9+v9, l11=l10+v10, l12=l11+v11, l13=l12+v12,
        l14=l13+v13, l15=l14+v14;
    int s = l15 + v15;
    int lane = t & 31, warp = t >> 5;
    int inc = s;
    #pragma unroll
    for (int d = 1; d < 32; d <<= 1) {
        int v = __shfl_up_sync(0xffffffffu, inc, d);
        if (lane >= d) inc += v;
    }
    if (lane == 31) wsum[warp] = inc;
    __syncthreads();
    if (warp == 0) {
        int v = wsum[lane];
        #pragma unroll
        for (int d = 1; d < 32; d <<= 1) {
            int u = __shfl_up_sync(0xffffffffu, v, d);
            if (lane >= d) v += u;
        }
        wsum[lane] = v;
    }
    __syncthreads();
    int p = (warp ? wsum[warp - 1] : 0) + (inc - s);
    int4 o0 = make_int4(p+l0,  p+l1,  p+l2,  p+l3);
    int4 o1 = make_int4(p+l4,  p+l5,  p+l6,  p+l7);
    int4 o2 = make_int4(p+l8,  p+l9,  p+l10, p+l11);
    int4 o3 = make_int4(p+l12, p+l13, p+l14, p+l15);
    *(int4*)&g_off[base + 0]  = o0;  *(int4*)&g_off[base + 4]  = o1;
    *(int4*)&g_off[base + 8]  = o2;  *(int4*)&g_off[base + 12] = o3;
    *(int4*)&g_deg[base + 0]  = o0;  *(int4*)&g_deg[base + 4]  = o1;
    *(int4*)&g_deg[base + 8]  = o2;  *(int4*)&g_deg[base + 12] = o3;
    if (t == 1023) g_off[N_NODES] = E_IN;
}
__global__ void scatter_kernel(const void* __restrict__ ei) {
    int e = blockIdx.x * blockDim.x + threadIdx.x;
    if (e >= E_IN) return;
    int src, dst; edge_nodes(ei, e, src, dst);
    int pos = atomicAdd(&g_deg[dst], 1);
    g_csr_src[pos] = src;
}

// ---------------- small GEMM (Nout<128): 64x64 tile, 4x4 microtile -----------
__global__ __launch_bounds__(256)
void gemm_kernel(int a_id, const float* __restrict__ W, const float* __restrict__ bias,
                 int c_id, int Nout, int K, int doRelu) {
    const float* A = (const float*)buf_ptr(a_id);
    float* C = buf_ptr(c_id);

    __shared__ float As[16][64];
    __shared__ float Ws[16][64];
    const int tid = threadIdx.x;
    const int tx = tid & 15, ty = tid >> 4;
    const int m0 = blockIdx.y * 64;
    const int n0 = blockIdx.x * 64;
    const int lr = tid >> 2;
    const int lc = (tid & 3) * 4;

    float acc[4][4];
    #pragma unroll
    for (int i = 0; i < 4; i++)
        #pragma unroll
        for (int j = 0; j < 4; j++) acc[i][j] = 0.f;

    for (int kt = 0; kt < K; kt += 16) {
        float4 av = *(const float4*)&A[(size_t)(m0 + lr) * K + kt + lc];
        As[lc + 0][lr] = av.x; As[lc + 1][lr] = av.y;
        As[lc + 2][lr] = av.z; As[lc + 3][lr] = av.w;
        float4 wv = make_float4(0.f, 0.f, 0.f, 0.f);
        if (n0 + lr < Nout)
            wv = *(const float4*)&W[(size_t)(n0 + lr) * K + kt + lc];
        Ws[lc + 0][lr] = wv.x; Ws[lc + 1][lr] = wv.y;
        Ws[lc + 2][lr] = wv.z; Ws[lc + 3][lr] = wv.w;
        __syncthreads();
        #pragma unroll
        for (int k = 0; k < 16; k++) {
            float4 a = *(const float4*)&As[k][ty * 4];
            float4 b = *(const float4*)&Ws[k][tx * 4];
            acc[0][0] = fmaf(a.x, b.x, acc[0][0]); acc[0][1] = fmaf(a.x, b.y, acc[0][1]);
            acc[0][2] = fmaf(a.x, b.z, acc[0][2]); acc[0][3] = fmaf(a.x, b.w, acc[0][3]);
            acc[1][0] = fmaf(a.y, b.x, acc[1][0]); acc[1][1] = fmaf(a.y, b.y, acc[1][1]);
            acc[1][2] = fmaf(a.y, b.z, acc[1][2]); acc[1][3] = fmaf(a.y, b.w, acc[1][3]);
            acc[2][0] = fmaf(a.z, b.x, acc[2][0]); acc[2][1] = fmaf(a.z, b.y, acc[2][1]);
            acc[2][2] = fmaf(a.z, b.z, acc[2][2]); acc[2][3] = fmaf(a.z, b.w, acc[2][3]);
            acc[3][0] = fmaf(a.w, b.x, acc[3][0]); acc[3][1] = fmaf(a.w, b.y, acc[3][1]);
            acc[3][2] = fmaf(a.w, b.z, acc[3][2]); acc[3][3] = fmaf(a.w, b.w, acc[3][3]);
        }
        __syncthreads();
    }

    const int col = n0 + tx * 4;
    if (col < Nout) {
        float bx = bias[col], by = bias[col + 1], bz = bias[col + 2], bw = bias[col + 3];
        #pragma unroll
        for (int i = 0; i < 4; i++) {
            int row = m0 + ty * 4 + i;
            float4 v = make_float4(acc[i][0] + bx, acc[i][1] + by,
                                   acc[i][2] + bz, acc[i][3] + bw);
            if (doRelu) {
                v.x = fmaxf(v.x, 0.f); v.y = fmaxf(v.y, 0.f);
                v.z = fmaxf(v.z, 0.f); v.w = fmaxf(v.w, 0.f);
            }
            *(float4*)&C[(size_t)row * Nout + col] = v;
        }
    }
}

// ---------------- attention scores: warp per (node, head) --------------------
__global__ void attn_scores_kernel(const float* __restrict__ att_src,
                                   const float* __restrict__ att_dst) {
    int gw = (blockIdx.x * blockDim.x + threadIdx.x) >> 5;
    int lane = threadIdx.x & 31;
    if (gw >= N_NODES * HEADS) return;
    int node = gw >> 1, head = gw & 1;
    const float* hp = g_h + (size_t)node * F_DIM + head * OUT_CH + lane * 8;
    const float* sp = att_src + head * OUT_CH + lane * 8;
    const float* dp = att_dst + head * OUT_CH + lane * 8;
    float4 h0 = *(const float4*)hp,  h1 = *(const float4*)(hp + 4);
    float4 s0 = *(const float4*)sp,  s1 = *(const float4*)(sp + 4);
    float4 d0 = *(const float4*)dp,  d1 = *(const float4*)(dp + 4);
    float s = h0.x * s0.x + h0.y * s0.y + h0.z * s0.z + h0.w * s0.w
            + h1.x * s1.x + h1.y * s1.y + h1.z * s1.z + h1.w * s1.w;
    float d = h0.x * d0.x + h0.y * d0.y + h0.z * d0.z + h0.w * d0.w
            + h1.x * d1.x + h1.y * d1.y + h1.z * d1.z + h1.w * d1.w;
    #pragma unroll
    for (int o = 16; o; o >>= 1) {
        s += __shfl_xor_sync(0xffffffffu, s, o);
        d += __shfl_xor_sync(0xffffffffu, d, o);
    }
    if (lane == 0) { g_as[gw] = s; g_ad[gw] = d; }
}

// ---------------- fused GAT: softmax + aggregate + bias + relu + bf16 split --
__global__ __launch_bounds__(128)
void gat_agg_kernel(const float* __restrict__ conv_b) {
    const int dst = blockIdx.x;
    const int t = threadIdx.x;
    __shared__ float red[128];
    __shared__ float sh_a0[128], sh_a1[128];
    __shared__ int   sh_src[128];
    __shared__ float sm0, sm1, ss0, ss1;

    const int off = g_off[dst];
    const int deg = g_off[dst + 1] - off;
    const float ad0 = g_ad[dst * 2], ad1 = g_ad[dst * 2 + 1];
    const float self0 = lrelu(g_as[dst * 2] + ad0);
    const float self1 = lrelu(g_as[dst * 2 + 1] + ad1);

    float m0 = self0, m1 = self1;
    for (int j = t; j < deg; j += 128) {
        int s = g_csr_src[off + j];
        m0 = fmaxf(m0, lrelu(g_as[s * 2] + ad0));
        m1 = fmaxf(m1, lrelu(g_as[s * 2 + 1] + ad1));
    }
    red[t] = m0; __syncthreads();
    for (int d = 64; d; d >>= 1) { if (t < d) red[t] = fmaxf(red[t], red[t + d]); __syncthreads(); }
    if (t == 0) sm0 = red[0];
    __syncthreads();
    red[t] = m1; __syncthreads();
    for (int d = 64; d; d >>= 1) { if (t < d) red[t] = fmaxf(red[t], red[t + d]); __syncthreads(); }
    if (t == 0) sm1 = red[0];
    __syncthreads();
    m0 = sm0; m1 = sm1;

    float s0 = (t == 0) ? expf(self0 - m0) : 0.f;
    float s1 = (t == 0) ? expf(self1 - m1) : 0.f;
    for (int j = t; j < deg; j += 128) {
        int s = g_csr_src[off + j];
        s0 += expf(lrelu(g_as[s * 2] + ad0) - m0);
        s1 += expf(lrelu(g_as[s * 2 + 1] + ad1) - m1);
    }
    red[t] = s0; __syncthreads();
    for (int d = 64; d; d >>= 1) { if (t < d) red[t] += red[t + d]; __syncthreads(); }
    if (t == 0) ss0 = red[0];
    __syncthreads();
    red[t] = s1; __syncthreads();
    for (int d = 64; d; d >>= 1) { if (t < d) red[t] += red[t + d]; __syncthreads(); }
    if (t == 0) ss1 = red[0];
    __syncthreads();
    const float rs0 = 1.f / ss0, rs1 = 1.f / ss1;

    const int head = t >> 6;
    const float mself  = head ? self1 : self0;
    const float mmax   = head ? sm1 : sm0;
    const float rss    = head ? rs1 : rs0;
    const float a_self = expf(mself - mmax) * rss;

    float4 v = *(const float4*)&g_h[(size_t)dst * F_DIM + t * 4];
    float4 acc = make_float4(a_self * v.x, a_self * v.y, a_self * v.z, a_self * v.w);

    for (int c = 0; c < deg; c += 128) {
        int j = c + t;
        if (j < deg) {
            int s = g_csr_src[off + j];
            sh_src[t] = s;
            sh_a0[t] = expf(lrelu(g_as[s * 2] + ad0) - sm0) * rs0;
            sh_a1[t] = expf(lrelu(g_as[s * 2 + 1] + ad1) - sm1) * rs1;
        }
        __syncthreads();
        int cnt = min(128, deg - c);
        for (int j2 = 0; j2 < cnt; j2++) {
            const float4 hv = *(const float4*)&g_h[(size_t)sh_src[j2] * F_DIM + t * 4];
            float a = head ? sh_a1[j2] : sh_a0[j2];
            acc.x = fmaf(a, hv.x, acc.x);
            acc.y = fmaf(a, hv.y, acc.y);
            acc.z = fmaf(a, hv.z, acc.z);
            acc.w = fmaf(a, hv.w, acc.w);
        }
        __syncthreads();
    }

    float4 b = *(const float4*)&conv_b[t * 4];
    acc.x = fmaxf(acc.x + b.x, 0.f);
    acc.y = fmaxf(acc.y + b.y, 0.f);
    acc.z = fmaxf(acc.z + b.z, 0.f);
    acc.w = fmaxf(acc.w + b.w, 0.f);
    __nv_bfloat162 h0, l0, h1, l1;
    split2(acc.x, acc.y, h0, l0);
    split2(acc.z, acc.w, h1, l1);
    size_t idx = (size_t)dst * F_DIM + t * 4;
    *(__nv_bfloat162*)&g_ah[idx]     = h0;
    *(__nv_bfloat162*)&g_ah[idx + 2] = h1;
    *(__nv_bfloat162*)&g_al[idx]     = l0;
    *(__nv_bfloat162*)&g_al[idx + 2] = l1;
}

// ---------------- last MLP layer: 32 -> 3 ------------------------------------
__global__ __launch_bounds__(256)
void final_layer_kernel(const float* __restrict__ W4, const float* __restrict__ b4) {
    __shared__ float w[3][32];
    __shared__ float bb[3];
    int tid = threadIdx.x;
    if (tid < 96) w[tid / 32][tid & 31] = W4[tid];
    if (tid < 3)  bb[tid] = b4[tid];
    __syncthreads();
    int n = blockIdx.x * blockDim.x + tid;
    if (n >= N_NODES) return;
    const float4* hp = (const float4*)(g_h4 + (size_t)n * 32);
    float a0 = bb[0], a1 = bb[1], a2 = bb[2];
    #pragma unroll
    for (int q = 0; q < 8; q++) {
        float4 v = hp[q];
        a0 = fmaf(v.x, w[0][q*4+0], a0); a0 = fmaf(v.y, w[0][q*4+1], a0);
        a0 = fmaf(v.z, w[0][q*4+2], a0); a0 = fmaf(v.w, w[0][q*4+3], a0);
        a1 = fmaf(v.x, w[1][q*4+0], a1); a1 = fmaf(v.y, w[1][q*4+1], a1);
        a1 = fmaf(v.z, w[1][q*4+2], a1); a1 = fmaf(v.w, w[1][q*4+3], a1);
        a2 = fmaf(v.x, w[2][q*4+0], a2); a2 = fmaf(v.y, w[2][q*4+1], a2);
        a2 = fmaf(v.z, w[2][q*4+2], a2); a2 = fmaf(v.w, w[2][q*4+3], a2);
    }
    ((float4*)g_h5)[n] = make_float4(a0, a1, a2, 0.f);
}

// ---------------- pairwise distances ------------------------------------------
__global__ __launch_bounds__(256)
void cdist_kernel(float* __restrict__ out) {
    __shared__ float4 rp[128];
    __shared__ float4 cp[128];
    int tid = threadIdx.x;
    int rb = blockIdx.y * 128, cb = blockIdx.x * 128;
    if (tid < 128) rp[tid] = ((const float4*)g_h5)[rb + tid];
    else           cp[tid - 128] = ((const float4*)g_h5)[cb + tid - 128];
    __syncthreads();
    int tx = tid & 31, ty = tid >> 5;
    float4 q0 = cp[tx * 4 + 0], q1 = cp[tx * 4 + 1],
           q2 = cp[tx * 4 + 2], q3 = cp[tx * 4 + 3];
    #pragma unroll
    for (int j = 0; j < 16; j++) {
        int r = j * 8 + ty;
        float4 p = rp[r];
        float dx, dy, dz, d2;
        float4 o;
        dx = p.x - q0.x; dy = p.y - q0.y; dz = p.z - q0.z;
        d2 = fmaf(dx, dx, fmaf(dy, dy, dz * dz)); o.x = fast_sqrt(d2);
        dx = p.x - q1.x; dy = p.y - q1.y; dz = p.z - q1.z;
        d2 = fmaf(dx, dx, fmaf(dy, dy, dz * dz)); o.y = fast_sqrt(d2);
        dx = p.x - q2.x; dy = p.y - q2.y; dz = p.z - q2.z;
        d2 = fmaf(dx, dx, fmaf(dy, dy, dz * dz)); o.z = fast_sqrt(d2);
        dx = p.x - q3.x; dy = p.y - q3.y; dz = p.z - q3.z;
        d2 = fmaf(dx, dx, fmaf(dy, dy, dz * dz)); o.w = fast_sqrt(d2);
        __stcs((float4*)&out[(size_t)(rb + r) * N_NODES + cb + tx * 4], o);
    }
}

// ---------------- launch -------------------------------------------------------
extern "C" void kernel_launch(void* const* d_in, const int* in_sizes, int n_in,
                              void* d_out, int out_size) {
    const float* x       = (const float*)d_in[0];
    const void*  ei      = (const void*)d_in[1];
    const float* conv_W  = (const float*)d_in[2];
    const float* att_src = (const float*)d_in[3];
    const float* att_dst = (const float*)d_in[4];
    const float* conv_b  = (const float*)d_in[5];
    const float* Wa = (const float*)d_in[6];  const float* ba = (const float*)d_in[7];
    const float* W1 = (const float*)d_in[8];  const float* b1 = (const float*)d_in[9];
    const float* W2 = (const float*)d_in[10]; const float* b2 = (const float*)d_in[11];
    const float* W3 = (const float*)d_in[12]; const float* b3 = (const float*)d_in[13];
    const float* W4 = (const float*)d_in[14]; const float* b4 = (const float*)d_in[15];
    float*       out = (float*)d_out;

    detect_idx_kernel<<<1, 32>>>(ei);                                        // 1
    split_kernel<<<(N_NODES * IN_DIM / 4 + 255) / 256, 256>>>(x, N_NODES * IN_DIM / 4, 0);      // 2
    split_kernel<<<(F_DIM * IN_DIM / 4 + 255) / 256, 256>>>(conv_W, F_DIM * IN_DIM / 4, 1);     // 3
    // conv GEMM: h = x @ conv_W^T  (launch #4, profiled)
    gemm_tc_kernel<<<dim3(F_DIM / 128, N_NODES / 128), 128>>>(nullptr, BUF_H, F_DIM, IN_DIM, 0, 0, 0);

    // CSR build
    zero_deg_kernel<<<(N_NODES + 255) / 256, 256>>>();
    hist_kernel<<<(E_IN + 255) / 256, 256>>>(ei);
    scan_kernel<<<1, 1024>>>();
    scatter_kernel<<<(E_IN + 255) / 256, 256>>>(ei);

    attn_scores_kernel<<<(N_NODES * HEADS * 32 + 255) / 256, 256>>>(att_src, att_dst);
    gat_agg_kernel<<<N_NODES, 128>>>(conv_b);   // writes bf16 split to g_ah/g_al

    // Wa: [N,512] -> [N,256], input g_ah/g_al, output split to g_ah2/g_al2
    split_kernel<<<(256 * 512 / 4 + 255) / 256, 256>>>(Wa, 256 * 512 / 4, 1);
    gemm_tc_kernel<<<dim3(256 / 128, N_NODES / 128), 128>>>(ba, BUF_H, 256, 512, 1, 0, 1);

    // W1: [N,256] -> [N,128], input g_ah2/g_al2, output fp32 g_h2
    split_kernel<<<(128 * 256 / 4 + 255) / 256, 256>>>(W1, 128 * 256 / 4, 1);
    gemm_tc_kernel<<<dim3(128 / 128, N_NODES / 128), 128>>>(b1, BUF_H2, 128, 256, 1, 1, 0);

    // small layers fp32 SIMT
    gemm_kernel<<<dim3(1, N_NODES / 64), 256>>>(BUF_H2, W2, b2, BUF_H3, 64, 128, 1);
    gemm_kernel<<<dim3(1, N_NODES / 64), 256>>>(BUF_H3, W3, b3, BUF_H4, 32, 64, 1);
    final_layer_kernel<<<N_NODES / 256, 256>>>(W4, b4);

    cdist_kernel<<<dim3(N_NODES / 128, N_NODES / 128), 256>>>(out);
}

// round 11
// speedup vs baseline: 1.0612x; 1.0612x over previous
#include <cuda_runtime.h>
#include <cuda_bf16.h>
#include <math.h>

#define N_NODES 16384
#define IN_DIM  256
#define HEADS   2
#define OUT_CH  256
#define F_DIM   512
#define E_IN    524288

// ---------------- scratch (device globals) ----------------------------------
__device__ float    g_h   [N_NODES * F_DIM];
__device__ float    g_as  [N_NODES * HEADS];
__device__ float    g_ad  [N_NODES * HEADS];
__device__ int      g_deg [N_NODES];
__device__ int      g_off [N_NODES + 1];
__device__ int      g_csr_src[E_IN];
__device__ float    g_h2  [N_NODES * 128];
__device__ float    g_h3  [N_NODES * 64];
__device__ float    g_h4  [N_NODES * 32];
__device__ float    g_h5  [N_NODES * 4];     // x,y,z,|p|^2
__device__ int      g_is64;
__device__ __nv_bfloat16 g_ah [N_NODES * F_DIM];
__device__ __nv_bfloat16 g_al [N_NODES * F_DIM];
__device__ __nv_bfloat16 g_ah2[N_NODES * 256];
__device__ __nv_bfloat16 g_al2[N_NODES * 256];
__device__ __nv_bfloat16 g_wh[512 * 256];
__device__ __nv_bfloat16 g_wl[512 * 256];

#define BUF_H   0
#define BUF_H2  3
#define BUF_H3  4
#define BUF_H4  5
__device__ __forceinline__ float* buf_ptr(int id) {
    switch (id) {
        case BUF_H:   return g_h;
        case BUF_H2:  return g_h2;
        case BUF_H3:  return g_h3;
        default:      return g_h4;
    }
}

// ---------------- helpers ---------------------------------------------------
__device__ __forceinline__ float lrelu(float v) { return v > 0.f ? v : 0.2f * v; }

__device__ __forceinline__ float rsqrt_approx(float x) {
    float r;
    asm("rsqrt.approx.f32 %0, %1;" : "=f"(r) : "f"(x));
    return r;
}

__device__ __forceinline__ void mma_bf16(float* c, const unsigned* a, const unsigned* b) {
    asm volatile(
        "mma.sync.aligned.m16n8k16.row.col.f32.bf16.bf16.f32 "
        "{%0,%1,%2,%3}, {%4,%5,%6,%7}, {%8,%9}, {%0,%1,%2,%3};"
        : "+f"(c[0]), "+f"(c[1]), "+f"(c[2]), "+f"(c[3])
        : "r"(a[0]), "r"(a[1]), "r"(a[2]), "r"(a[3]), "r"(b[0]), "r"(b[1]));
}

__device__ __forceinline__ void cp_async16(void* smem_dst, const void* gsrc) {
    unsigned s = (unsigned)__cvta_generic_to_shared(smem_dst);
    asm volatile("cp.async.ca.shared.global [%0], [%1], 16;" :: "r"(s), "l"(gsrc));
}
__device__ __forceinline__ void cp_commit() { asm volatile("cp.async.commit_group;"); }
__device__ __forceinline__ void cp_wait0()  { asm volatile("cp.async.wait_group 0;" ::: "memory"); }

__device__ __forceinline__ void split2(float a, float b, __nv_bfloat162& h, __nv_bfloat162& l) {
    __nv_bfloat16 ha = __float2bfloat16_rn(a);
    __nv_bfloat16 hb = __float2bfloat16_rn(b);
    h.x = ha; h.y = hb;
    l.x = __float2bfloat16_rn(a - __bfloat162float(ha));
    l.y = __float2bfloat16_rn(b - __bfloat162float(hb));
}

// ---------------- split fp32 -> bf16 hi/lo (x and weights) -------------------
__global__ void split_kernel(const float* __restrict__ A, int n4, int dest) {
    int i = blockIdx.x * blockDim.x + threadIdx.x;
    if (i >= n4) return;
    float4 v = ((const float4*)A)[i];
    __nv_bfloat162 h0, h1, l0, l1;
    split2(v.x, v.y, h0, l0);
    split2(v.z, v.w, h1, l1);
    __nv_bfloat162* dh = dest ? (__nv_bfloat162*)g_wh : (__nv_bfloat162*)g_ah;
    __nv_bfloat162* dl = dest ? (__nv_bfloat162*)g_wl : (__nv_bfloat162*)g_al;
    dh[i * 2] = h0; dh[i * 2 + 1] = h1;
    dl[i * 2] = l0; dl[i * 2 + 1] = l1;
}

// ---------------- tensor-core GEMM (R9 config: 256 thr, 64x32 warp tile) ------
#define SP 24
__global__ __launch_bounds__(256, 2)
void gemm_tc_kernel(const float* __restrict__ bias, int c_id,
                    int Nout, int K, int doRelu, int in_sel, int out_mode) {
    const __nv_bfloat16* Ah = in_sel ? g_ah2 : g_ah;
    const __nv_bfloat16* Al = in_sel ? g_al2 : g_al;
    __shared__ __align__(16) __nv_bfloat16 sAh[2][128 * SP];
    __shared__ __align__(16) __nv_bfloat16 sAl[2][128 * SP];
    __shared__ __align__(16) __nv_bfloat16 sBh[2][128 * SP];
    __shared__ __align__(16) __nv_bfloat16 sBl[2][128 * SP];

    const int tid  = threadIdx.x;
    const int m0 = blockIdx.y * 128, n0 = blockIdx.x * 128;
    const int lrow = tid >> 1, lhalf = tid & 1;
    const size_t gA = (size_t)(m0 + lrow) * K + lhalf * 8;
    const size_t gB = (size_t)(n0 + lrow) * K + lhalf * 8;
    const int sofs = lrow * SP + lhalf * 8;

    const int w = tid >> 5, lane = tid & 31;
    const int wm = (w & 1) * 64, wn = (w >> 1) * 32;
    const int gr = lane >> 2, tg = lane & 3;

    float acc[4][4][4];
    #pragma unroll
    for (int mt = 0; mt < 4; mt++)
        #pragma unroll
        for (int nt = 0; nt < 4; nt++)
            #pragma unroll
            for (int r = 0; r < 4; r++) acc[mt][nt][r] = 0.f;

    cp_async16(&sAh[0][sofs], &Ah[gA]);
    cp_async16(&sAl[0][sofs], &Al[gA]);
    cp_async16(&sBh[0][sofs], &g_wh[gB]);
    cp_async16(&sBl[0][sofs], &g_wl[gB]);
    cp_commit(); cp_wait0();
    __syncthreads();

    const int T = K >> 4;
    for (int t = 0; t < T; t++) {
        const int cur = t & 1;
        if (t + 1 < T) {
            const int nxt = cur ^ 1;
            int kt = (t + 1) << 4;
            cp_async16(&sAh[nxt][sofs], &Ah[gA + kt]);
            cp_async16(&sAl[nxt][sofs], &Al[gA + kt]);
            cp_async16(&sBh[nxt][sofs], &g_wh[gB + kt]);
            cp_async16(&sBl[nxt][sofs], &g_wl[gB + kt]);
            cp_commit();
        }

        unsigned ah[4][4], al[4][4], bh[4][2], bl[4][2];
        #pragma unroll
        for (int mt = 0; mt < 4; mt++) {
            int r = wm + mt * 16 + gr;
            ah[mt][0] = *(const unsigned*)&sAh[cur][r * SP + 2 * tg];
            ah[mt][1] = *(const unsigned*)&sAh[cur][(r + 8) * SP + 2 * tg];
            ah[mt][2] = *(const unsigned*)&sAh[cur][r * SP + 8 + 2 * tg];
            ah[mt][3] = *(const unsigned*)&sAh[cur][(r + 8) * SP + 8 + 2 * tg];
            al[mt][0] = *(const unsigned*)&sAl[cur][r * SP + 2 * tg];
            al[mt][1] = *(const unsigned*)&sAl[cur][(r + 8) * SP + 2 * tg];
            al[mt][2] = *(const unsigned*)&sAl[cur][r * SP + 8 + 2 * tg];
            al[mt][3] = *(const unsigned*)&sAl[cur][(r + 8) * SP + 8 + 2 * tg];
        }
        #pragma unroll
        for (int nt = 0; nt < 4; nt++) {
            int cn = wn + nt * 8 + gr;
            bh[nt][0] = *(const unsigned*)&sBh[cur][cn * SP + 2 * tg];
            bh[nt][1] = *(const unsigned*)&sBh[cur][cn * SP + 8 + 2 * tg];
            bl[nt][0] = *(const unsigned*)&sBl[cur][cn * SP + 2 * tg];
            bl[nt][1] = *(const unsigned*)&sBl[cur][cn * SP + 8 + 2 * tg];
        }
        #pragma unroll
        for (int mt = 0; mt < 4; mt++)
            #pragma unroll
            for (int nt = 0; nt < 4; nt++) {
                mma_bf16(acc[mt][nt], ah[mt], bh[nt]);
                mma_bf16(acc[mt][nt], ah[mt], bl[nt]);
                mma_bf16(acc[mt][nt], al[mt], bh[nt]);
            }

        if (t + 1 < T) cp_wait0();
        __syncthreads();
    }

    float* C = buf_ptr(c_id);
    #pragma unroll
    for (int mt = 0; mt < 4; mt++) {
        int row = m0 + wm + mt * 16 + gr;
        #pragma unroll
        for (int nt = 0; nt < 4; nt++) {
            int col = n0 + wn + nt * 8 + 2 * tg;
            float b0 = bias ? bias[col] : 0.f;
            float b1 = bias ? bias[col + 1] : 0.f;
            float o0 = acc[mt][nt][0] + b0, o1 = acc[mt][nt][1] + b1;
            float o2 = acc[mt][nt][2] + b0, o3 = acc[mt][nt][3] + b1;
            if (doRelu) {
                o0 = fmaxf(o0, 0.f); o1 = fmaxf(o1, 0.f);
                o2 = fmaxf(o2, 0.f); o3 = fmaxf(o3, 0.f);
            }
            if (out_mode == 0) {
                *(float2*)&C[(size_t)row * Nout + col]       = make_float2(o0, o1);
                *(float2*)&C[(size_t)(row + 8) * Nout + col] = make_float2(o2, o3);
            } else {
                __nv_bfloat162 h0, l0, h1, l1;
                split2(o0, o1, h0, l0);
                split2(o2, o3, h1, l1);
                *(__nv_bfloat162*)&g_ah2[(size_t)row * Nout + col]       = h0;
                *(__nv_bfloat162*)&g_al2[(size_t)row * Nout + col]       = l0;
                *(__nv_bfloat162*)&g_ah2[(size_t)(row + 8) * Nout + col] = h1;
                *(__nv_bfloat162*)&g_al2[(size_t)(row + 8) * Nout + col] = l1;
            }
        }
    }
}

// ---------------- edge_index dtype probe -------------------------------------
__global__ void detect_idx_kernel(const void* __restrict__ ei) {
    if (threadIdx.x == 0 && blockIdx.x == 0) {
        const long long* p = (const long long*)ei;
        int ok64 = 1;
        for (int i = 0; i < 256; i++) {
            long long v = p[i];
            if (v < 0 || v >= N_NODES) { ok64 = 0; break; }
        }
        g_is64 = ok64;
    }
}
__device__ __forceinline__ void edge_nodes(const void* __restrict__ ei, int e,
                                           int& src, int& dst) {
    if (g_is64) {
        const long long* p = (const long long*)ei;
        src = (int)p[e]; dst = (int)p[E_IN + e];
    } else {
        const int* p = (const int*)ei;
        src = p[e]; dst = p[E_IN + e];
    }
    src = min(max(src, 0), N_NODES - 1);
    dst = min(max(dst, 0), N_NODES - 1);
}

// ---------------- CSR build ---------------------------------------------------
__global__ void zero_deg_kernel() {
    int i = blockIdx.x * blockDim.x + threadIdx.x;
    if (i < N_NODES) g_deg[i] = 0;
}
__global__ void hist_kernel(const void* __restrict__ ei) {
    int e = blockIdx.x * blockDim.x + threadIdx.x;
    if (e >= E_IN) return;
    int src, dst; edge_nodes(ei, e, src, dst);
    atomicAdd(&g_deg[dst], 1);
}
__global__ __launch_bounds__(1024)
void scan_kernel() {
    __shared__ int wsum[32];
    int t = threadIdx.x;
    int base = t * 16;
    int4 d0 = *(const int4*)&g_deg[base + 0];
    int4 d1 = *(const int4*)&g_deg[base + 4];
    int4 d2 = *(const int4*)&g_deg[base + 8];
    int4 d3 = *(const int4*)&g_deg[base + 12];
    int v0 = d0.x, v1 = d0.y, v2 = d0.z, v3 = d0.w;
    int v4 = d1.x, v5 = d1.y, v6 = d1.z, v7 = d1.w;
    int v8 = d2.x, v9 = d2.y, v10 = d2.z, v11 = d2.w;
    int v12 = d3.x, v13 = d3.y, v14 = d3.z, v15 = d3.w;
    int l0=0, l1=v0, l2=l1+v1, l3=l2+v2, l4=l3+v3, l5=l4+v4, l6=l5+v5, l7=l6+v6,
        l8=l7+v7, l9=l8+v8, l10=l9+v9, l11=l10+v10, l12=l11+v11, l13=l12+v12,
        l14=l13+v13, l15=l14+v14;
    int s = l15 + v15;
    int lane = t & 31, warp = t >> 5;
    int inc = s;
    #pragma unroll
    for (int d = 1; d < 32; d <<= 1) {
        int v = __shfl_up_sync(0xffffffffu, inc, d);
        if (lane >= d) inc += v;
    }
    if (lane == 31) wsum[warp] = inc;
    __syncthreads();
    if (warp == 0) {
        int v = wsum[lane];
        #pragma unroll
        for (int d = 1; d < 32; d <<= 1) {
            int u = __shfl_up_sync(0xffffffffu, v, d);
            if (lane >= d) v += u;
        }
        wsum[lane] = v;
    }
    __syncthreads();
    int p = (warp ? wsum[warp - 1] : 0) + (inc - s);
    int4 o0 = make_int4(p+l0,  p+l1,  p+l2,  p+l3);
    int4 o1 = make_int4(p+l4,  p+l5,  p+l6,  p+l7);
    int4 o2 = make_int4(p+l8,  p+l9,  p+l10, p+l11);
    int4 o3 = make_int4(p+l12, p+l13, p+l14, p+l15);
    *(int4*)&g_off[base + 0]  = o0;  *(int4*)&g_off[base + 4]  = o1;
    *(int4*)&g_off[base + 8]  = o2;  *(int4*)&g_off[base + 12] = o3;
    *(int4*)&g_deg[base + 0]  = o0;  *(int4*)&g_deg[base + 4]  = o1;
    *(int4*)&g_deg[base + 8]  = o2;  *(int4*)&g_deg[base + 12] = o3;
    if (t == 1023) g_off[N_NODES] = E_IN;
}
__global__ void scatter_kernel(const void* __restrict__ ei) {
    int e = blockIdx.x * blockDim.x + threadIdx.x;
    if (e >= E_IN) return;
    int src, dst; edge_nodes(ei, e, src, dst);
    int pos = atomicAdd(&g_deg[dst], 1);
    g_csr_src[pos] = src;
}

// ---------------- small GEMM (Nout<128): 64x64 tile, 4x4 microtile -----------
__global__ __launch_bounds__(256)
void gemm_kernel(int a_id, const float* __restrict__ W, const float* __restrict__ bias,
                 int c_id, int Nout, int K, int doRelu) {
    const float* A = (const float*)buf_ptr(a_id);
    float* C = buf_ptr(c_id);

    __shared__ float As[16][64];
    __shared__ float Ws[16][64];
    const int tid = threadIdx.x;
    const int tx = tid & 15, ty = tid >> 4;
    const int m0 = blockIdx.y * 64;
    const int n0 = blockIdx.x * 64;
    const int lr = tid >> 2;
    const int lc = (tid & 3) * 4;

    float acc[4][4];
    #pragma unroll
    for (int i = 0; i < 4; i++)
        #pragma unroll
        for (int j = 0; j < 4; j++) acc[i][j] = 0.f;

    for (int kt = 0; kt < K; kt += 16) {
        float4 av = *(const float4*)&A[(size_t)(m0 + lr) * K + kt + lc];
        As[lc + 0][lr] = av.x; As[lc + 1][lr] = av.y;
        As[lc + 2][lr] = av.z; As[lc + 3][lr] = av.w;
        float4 wv = make_float4(0.f, 0.f, 0.f, 0.f);
        if (n0 + lr < Nout)
            wv = *(const float4*)&W[(size_t)(n0 + lr) * K + kt + lc];
        Ws[lc + 0][lr] = wv.x; Ws[lc + 1][lr] = wv.y;
        Ws[lc + 2][lr] = wv.z; Ws[lc + 3][lr] = wv.w;
        __syncthreads();
        #pragma unroll
        for (int k = 0; k < 16; k++) {
            float4 a = *(const float4*)&As[k][ty * 4];
            float4 b = *(const float4*)&Ws[k][tx * 4];
            acc[0][0] = fmaf(a.x, b.x, acc[0][0]); acc[0][1] = fmaf(a.x, b.y, acc[0][1]);
            acc[0][2] = fmaf(a.x, b.z, acc[0][2]); acc[0][3] = fmaf(a.x, b.w, acc[0][3]);
            acc[1][0] = fmaf(a.y, b.x, acc[1][0]); acc[1][1] = fmaf(a.y, b.y, acc[1][1]);
            acc[1][2] = fmaf(a.y, b.z, acc[1][2]); acc[1][3] = fmaf(a.y, b.w, acc[1][3]);
            acc[2][0] = fmaf(a.z, b.x, acc[2][0]); acc[2][1] = fmaf(a.z, b.y, acc[2][1]);
            acc[2][2] = fmaf(a.z, b.z, acc[2][2]); acc[2][3] = fmaf(a.z, b.w, acc[2][3]);
            acc[3][0] = fmaf(a.w, b.x, acc[3][0]); acc[3][1] = fmaf(a.w, b.y, acc[3][1]);
            acc[3][2] = fmaf(a.w, b.z, acc[3][2]); acc[3][3] = fmaf(a.w, b.w, acc[3][3]);
        }
        __syncthreads();
    }

    const int col = n0 + tx * 4;
    if (col < Nout) {
        float bx = bias[col], by = bias[col + 1], bz = bias[col + 2], bw = bias[col + 3];
        #pragma unroll
        for (int i = 0; i < 4; i++) {
            int row = m0 + ty * 4 + i;
            float4 v = make_float4(acc[i][0] + bx, acc[i][1] + by,
                                   acc[i][2] + bz, acc[i][3] + bw);
            if (doRelu) {
                v.x = fmaxf(v.x, 0.f); v.y = fmaxf(v.y, 0.f);
                v.z = fmaxf(v.z, 0.f); v.w = fmaxf(v.w, 0.f);
            }
            *(float4*)&C[(size_t)row * Nout + col] = v;
        }
    }
}

// ---------------- attention scores: warp per (node, head) --------------------
__global__ void attn_scores_kernel(const float* __restrict__ att_src,
                                   const float* __restrict__ att_dst) {
    int gw = (blockIdx.x * blockDim.x + threadIdx.x) >> 5;
    int lane = threadIdx.x & 31;
    if (gw >= N_NODES * HEADS) return;
    int node = gw >> 1, head = gw & 1;
    const float* hp = g_h + (size_t)node * F_DIM + head * OUT_CH + lane * 8;
    const float* sp = att_src + head * OUT_CH + lane * 8;
    const float* dp = att_dst + head * OUT_CH + lane * 8;
    float4 h0 = *(const float4*)hp,  h1 = *(const float4*)(hp + 4);
    float4 s0 = *(const float4*)sp,  s1 = *(const float4*)(sp + 4);
    float4 d0 = *(const float4*)dp,  d1 = *(const float4*)(dp + 4);
    float s = h0.x * s0.x + h0.y * s0.y + h0.z * s0.z + h0.w * s0.w
            + h1.x * s1.x + h1.y * s1.y + h1.z * s1.z + h1.w * s1.w;
    float d = h0.x * d0.x + h0.y * d0.y + h0.z * d0.z + h0.w * d0.w
            + h1.x * d1.x + h1.y * d1.y + h1.z * d1.z + h1.w * d1.w;
    #pragma unroll
    for (int o = 16; o; o >>= 1) {
        s += __shfl_xor_sync(0xffffffffu, s, o);
        d += __shfl_xor_sync(0xffffffffu, d, o);
    }
    if (lane == 0) { g_as[gw] = s; g_ad[gw] = d; }
}

// ---------------- fused GAT: softmax + aggregate + bias + relu + bf16 split --
__global__ __launch_bounds__(128)
void gat_agg_kernel(const float* __restrict__ conv_b) {
    const int dst = blockIdx.x;
    const int t = threadIdx.x;
    __shared__ float red[128];
    __shared__ float sh_a0[128], sh_a1[128];
    __shared__ int   sh_src[128];
    __shared__ float sm0, sm1, ss0, ss1;

    const int off = g_off[dst];
    const int deg = g_off[dst + 1] - off;
    const float ad0 = g_ad[dst * 2], ad1 = g_ad[dst * 2 + 1];
    const float self0 = lrelu(g_as[dst * 2] + ad0);
    const float self1 = lrelu(g_as[dst * 2 + 1] + ad1);

    float m0 = self0, m1 = self1;
    for (int j = t; j < deg; j += 128) {
        int s = g_csr_src[off + j];
        m0 = fmaxf(m0, lrelu(g_as[s * 2] + ad0));
        m1 = fmaxf(m1, lrelu(g_as[s * 2 + 1] + ad1));
    }
    red[t] = m0; __syncthreads();
    for (int d = 64; d; d >>= 1) { if (t < d) red[t] = fmaxf(red[t], red[t + d]); __syncthreads(); }
    if (t == 0) sm0 = red[0];
    __syncthreads();
    red[t] = m1; __syncthreads();
    for (int d = 64; d; d >>= 1) { if (t < d) red[t] = fmaxf(red[t], red[t + d]); __syncthreads(); }
    if (t == 0) sm1 = red[0];
    __syncthreads();
    m0 = sm0; m1 = sm1;

    float s0 = (t == 0) ? expf(self0 - m0) : 0.f;
    float s1 = (t == 0) ? expf(self1 - m1) : 0.f;
    for (int j = t; j < deg; j += 128) {
        int s = g_csr_src[off + j];
        s0 += expf(lrelu(g_as[s * 2] + ad0) - m0);
        s1 += expf(lrelu(g_as[s * 2 + 1] + ad1) - m1);
    }
    red[t] = s0; __syncthreads();
    for (int d = 64; d; d >>= 1) { if (t < d) red[t] += red[t + d]; __syncthreads(); }
    if (t == 0) ss0 = red[0];
    __syncthreads();
    red[t] = s1; __syncthreads();
    for (int d = 64; d; d >>= 1) { if (t < d) red[t] += red[t + d]; __syncthreads(); }
    if (t == 0) ss1 = red[0];
    __syncthreads();
    const float rs0 = 1.f / ss0, rs1 = 1.f / ss1;

    const int head = t >> 6;
    const float mself  = head ? self1 : self0;
    const float mmax   = head ? sm1 : sm0;
    const float rss    = head ? rs1 : rs0;
    const float a_self = expf(mself - mmax) * rss;

    float4 v = *(const float4*)&g_h[(size_t)dst * F_DIM + t * 4];
    float4 acc = make_float4(a_self * v.x, a_self * v.y, a_self * v.z, a_self * v.w);

    for (int c = 0; c < deg; c += 128) {
        int j = c + t;
        if (j < deg) {
            int s = g_csr_src[off + j];
            sh_src[t] = s;
            sh_a0[t] = expf(lrelu(g_as[s * 2] + ad0) - sm0) * rs0;
            sh_a1[t] = expf(lrelu(g_as[s * 2 + 1] + ad1) - sm1) * rs1;
        }
        __syncthreads();
        int cnt = min(128, deg - c);
        for (int j2 = 0; j2 < cnt; j2++) {
            const float4 hv = *(const float4*)&g_h[(size_t)sh_src[j2] * F_DIM + t * 4];
            float a = head ? sh_a1[j2] : sh_a0[j2];
            acc.x = fmaf(a, hv.x, acc.x);
            acc.y = fmaf(a, hv.y, acc.y);
            acc.z = fmaf(a, hv.z, acc.z);
            acc.w = fmaf(a, hv.w, acc.w);
        }
        __syncthreads();
    }

    float4 b = *(const float4*)&conv_b[t * 4];
    acc.x = fmaxf(acc.x + b.x, 0.f);
    acc.y = fmaxf(acc.y + b.y, 0.f);
    acc.z = fmaxf(acc.z + b.z, 0.f);
    acc.w = fmaxf(acc.w + b.w, 0.f);
    __nv_bfloat162 h0, l0, h1, l1;
    split2(acc.x, acc.y, h0, l0);
    split2(acc.z, acc.w, h1, l1);
    size_t idx = (size_t)dst * F_DIM + t * 4;
    *(__nv_bfloat162*)&g_ah[idx]     = h0;
    *(__nv_bfloat162*)&g_ah[idx + 2] = h1;
    *(__nv_bfloat162*)&g_al[idx]     = l0;
    *(__nv_bfloat162*)&g_al[idx + 2] = l1;
}

// ---------------- last MLP layer: 32 -> 3, also store |p|^2 -------------------
__global__ __launch_bounds__(256)
void final_layer_kernel(const float* __restrict__ W4, const float* __restrict__ b4) {
    __shared__ float w[3][32];
    __shared__ float bb[3];
    int tid = threadIdx.x;
    if (tid < 96) w[tid / 32][tid & 31] = W4[tid];
    if (tid < 3)  bb[tid] = b4[tid];
    __syncthreads();
    int n = blockIdx.x * blockDim.x + tid;
    if (n >= N_NODES) return;
    const float4* hp = (const float4*)(g_h4 + (size_t)n * 32);
    float a0 = bb[0], a1 = bb[1], a2 = bb[2];
    #pragma unroll
    for (int q = 0; q < 8; q++) {
        float4 v = hp[q];
        a0 = fmaf(v.x, w[0][q*4+0], a0); a0 = fmaf(v.y, w[0][q*4+1], a0);
        a0 = fmaf(v.z, w[0][q*4+2], a0); a0 = fmaf(v.w, w[0][q*4+3], a0);
        a1 = fmaf(v.x, w[1][q*4+0], a1); a1 = fmaf(v.y, w[1][q*4+1], a1);
        a1 = fmaf(v.z, w[1][q*4+2], a1); a1 = fmaf(v.w, w[1][q*4+3], a1);
        a2 = fmaf(v.x, w[2][q*4+0], a2); a2 = fmaf(v.y, w[2][q*4+1], a2);
        a2 = fmaf(v.z, w[2][q*4+2], a2); a2 = fmaf(v.w, w[2][q*4+3], a2);
    }
    float sq = fmaf(a0, a0, fmaf(a1, a1, a2 * a2));
    ((float4*)g_h5)[n] = make_float4(a0, a1, a2, sq);
}

// ---------------- pairwise distances: d2 = sp+sq-2*dot, MUFU rsqrt ------------
__global__ __launch_bounds__(256)
void cdist_kernel(float* __restrict__ out) {
    __shared__ float4 rp[128];
    __shared__ float4 cp[128];
    int tid = threadIdx.x;
    int rb = blockIdx.y * 128, cb = blockIdx.x * 128;
    if (tid < 128) rp[tid] = ((const float4*)g_h5)[rb + tid];
    else           cp[tid - 128] = ((const float4*)g_h5)[cb + tid - 128];
    __syncthreads();
    int tx = tid & 31, ty = tid >> 5;
    float4 q0 = cp[tx * 4 + 0], q1 = cp[tx * 4 + 1],
           q2 = cp[tx * 4 + 2], q3 = cp[tx * 4 + 3];
    #pragma unroll
    for (int j = 0; j < 16; j++) {
        int r = j * 8 + ty;
        float4 p = rp[r];
        float4 o;
        float t, d2;
        t = p.x * q0.x; t = fmaf(p.y, q0.y, t); t = fmaf(p.z, q0.z, t);
        d2 = fmaf(-2.f, t, p.w + q0.w); d2 = fmaxf(d2, 0.f);
        o.x = d2 * rsqrt_approx(fmaxf(d2, 1e-35f));
        t = p.x * q1.x; t = fmaf(p.y, q1.y, t); t = fmaf(p.z, q1.z, t);
        d2 = fmaf(-2.f, t, p.w + q1.w); d2 = fmaxf(d2, 0.f);
        o.y = d2 * rsqrt_approx(fmaxf(d2, 1e-35f));
        t = p.x * q2.x; t = fmaf(p.y, q2.y, t); t = fmaf(p.z, q2.z, t);
        d2 = fmaf(-2.f, t, p.w + q2.w); d2 = fmaxf(d2, 0.f);
        o.z = d2 * rsqrt_approx(fmaxf(d2, 1e-35f));
        t = p.x * q3.x; t = fmaf(p.y, q3.y, t); t = fmaf(p.z, q3.z, t);
        d2 = fmaf(-2.f, t, p.w + q3.w); d2 = fmaxf(d2, 0.f);
        o.w = d2 * rsqrt_approx(fmaxf(d2, 1e-35f));
        __stcs((float4*)&out[(size_t)(rb + r) * N_NODES + cb + tx * 4], o);
    }
}

// ---------------- launch -------------------------------------------------------
extern "C" void kernel_launch(void* const* d_in, const int* in_sizes, int n_in,
                              void* d_out, int out_size) {
    const float* x       = (const float*)d_in[0];
    const void*  ei      = (const void*)d_in[1];
    const float* conv_W  = (const float*)d_in[2];
    const float* att_src = (const float*)d_in[3];
    const float* att_dst = (const float*)d_in[4];
    const float* conv_b  = (const float*)d_in[5];
    const float* Wa = (const float*)d_in[6];  const float* ba = (const float*)d_in[7];
    const float* W1 = (const float*)d_in[8];  const float* b1 = (const float*)d_in[9];
    const float* W2 = (const float*)d_in[10]; const float* b2 = (const float*)d_in[11];
    const float* W3 = (const float*)d_in[12]; const float* b3 = (const float*)d_in[13];
    const float* W4 = (const float*)d_in[14]; const float* b4 = (const float*)d_in[15];
    float*       out = (float*)d_out;

    detect_idx_kernel<<<1, 32>>>(ei);                                        // 1
    split_kernel<<<(N_NODES * IN_DIM / 4 + 255) / 256, 256>>>(x, N_NODES * IN_DIM / 4, 0);      // 2
    split_kernel<<<(F_DIM * IN_DIM / 4 + 255) / 256, 256>>>(conv_W, F_DIM * IN_DIM / 4, 1);     // 3
    // conv GEMM: h = x @ conv_W^T  (launch #4, profiled)
    gemm_tc_kernel<<<dim3(F_DIM / 128, N_NODES / 128), 256>>>(nullptr, BUF_H, F_DIM, IN_DIM, 0, 0, 0);

    // CSR build
    zero_deg_kernel<<<(N_NODES + 255) / 256, 256>>>();
    hist_kernel<<<(E_IN + 255) / 256, 256>>>(ei);
    scan_kernel<<<1, 1024>>>();
    scatter_kernel<<<(E_IN + 255) / 256, 256>>>(ei);

    attn_scores_kernel<<<(N_NODES * HEADS * 32 + 255) / 256, 256>>>(att_src, att_dst);
    gat_agg_kernel<<<N_NODES, 128>>>(conv_b);   // writes bf16 split to g_ah/g_al

    // Wa: [N,512] -> [N,256]
    split_kernel<<<(256 * 512 / 4 + 255) / 256, 256>>>(Wa, 256 * 512 / 4, 1);
    gemm_tc_kernel<<<dim3(256 / 128, N_NODES / 128), 256>>>(ba, BUF_H, 256, 512, 1, 0, 1);

    // W1: [N,256] -> [N,128]
    split_kernel<<<(128 * 256 / 4 + 255) / 256, 256>>>(W1, 128 * 256 / 4, 1);
    gemm_tc_kernel<<<dim3(128 / 128, N_NODES / 128), 256>>>(b1, BUF_H2, 128, 256, 1, 1, 0);

    // small layers fp32 SIMT
    gemm_kernel<<<dim3(1, N_NODES / 64), 256>>>(BUF_H2, W2, b2, BUF_H3, 64, 128, 1);
    gemm_kernel<<<dim3(1, N_NODES / 64), 256>>>(BUF_H3, W3, b3, BUF_H4, 32, 64, 1);
    final_layer_kernel<<<N_NODES / 256, 256>>>(W4, b4);

    cdist_kernel<<<dim3(N_NODES / 128, N_NODES / 128), 256>>>(out);
}

// round 12
// speedup vs baseline: 1.1245x; 1.0596x over previous
#include <cuda_runtime.h>
#include <cuda_bf16.h>
#include <math.h>

#define N_NODES 16384
#define IN_DIM  256
#define HEADS   2
#define OUT_CH  256
#define F_DIM   512
#define E_IN    524288

// ---------------- scratch (device globals) ----------------------------------
__device__ float    g_h   [N_NODES * F_DIM];
__device__ float    g_as  [N_NODES * HEADS];
__device__ float    g_ad  [N_NODES * HEADS];
__device__ int      g_deg [N_NODES];
__device__ int      g_off [N_NODES + 1];
__device__ int      g_csr_src[E_IN];
__device__ float    g_h2  [N_NODES * 128];
__device__ float    g_h3  [N_NODES * 64];
__device__ float    g_h4  [N_NODES * 32];
__device__ float    g_h5  [N_NODES * 4];     // x,y,z,|p|^2
__device__ int      g_is64;
__device__ __nv_bfloat16 g_ah [N_NODES * F_DIM];
__device__ __nv_bfloat16 g_al [N_NODES * F_DIM];
__device__ __nv_bfloat16 g_ah2[N_NODES * 256];
__device__ __nv_bfloat16 g_al2[N_NODES * 256];
__device__ __nv_bfloat16 g_wh[512 * 256];
__device__ __nv_bfloat16 g_wl[512 * 256];

#define BUF_H   0
#define BUF_H2  3
#define BUF_H3  4
#define BUF_H4  5
__device__ __forceinline__ float* buf_ptr(int id) {
    switch (id) {
        case BUF_H:   return g_h;
        case BUF_H2:  return g_h2;
        case BUF_H3:  return g_h3;
        default:      return g_h4;
    }
}

// ---------------- helpers ---------------------------------------------------
__device__ __forceinline__ float lrelu(float v) { return v > 0.f ? v : 0.2f * v; }

__device__ __forceinline__ float rsqrt_approx(float x) {
    float r;
    asm("rsqrt.approx.f32 %0, %1;" : "=f"(r) : "f"(x));
    return r;
}

__device__ __forceinline__ void mma_bf16(float* c, const unsigned* a, const unsigned* b) {
    asm volatile(
        "mma.sync.aligned.m16n8k16.row.col.f32.bf16.bf16.f32 "
        "{%0,%1,%2,%3}, {%4,%5,%6,%7}, {%8,%9}, {%0,%1,%2,%3};"
        : "+f"(c[0]), "+f"(c[1]), "+f"(c[2]), "+f"(c[3])
        : "r"(a[0]), "r"(a[1]), "r"(a[2]), "r"(a[3]), "r"(b[0]), "r"(b[1]));
}

__device__ __forceinline__ void ldsm_x4(unsigned* r, unsigned saddr) {
    asm volatile("ldmatrix.sync.aligned.m8n8.x4.shared.b16 {%0,%1,%2,%3}, [%4];"
        : "=r"(r[0]), "=r"(r[1]), "=r"(r[2]), "=r"(r[3]) : "r"(saddr));
}

__device__ __forceinline__ void cp_async16(void* smem_dst, const void* gsrc) {
    unsigned s = (unsigned)__cvta_generic_to_shared(smem_dst);
    asm volatile("cp.async.ca.shared.global [%0], [%1], 16;" :: "r"(s), "l"(gsrc));
}
__device__ __forceinline__ void cp_commit() { asm volatile("cp.async.commit_group;"); }
__device__ __forceinline__ void cp_wait0()  { asm volatile("cp.async.wait_group 0;" ::: "memory"); }

__device__ __forceinline__ void split2(float a, float b, __nv_bfloat162& h, __nv_bfloat162& l) {
    __nv_bfloat16 ha = __float2bfloat16_rn(a);
    __nv_bfloat16 hb = __float2bfloat16_rn(b);
    h.x = ha; h.y = hb;
    l.x = __float2bfloat16_rn(a - __bfloat162float(ha));
    l.y = __float2bfloat16_rn(b - __bfloat162float(hb));
}

// ---------------- split fp32 -> bf16 hi/lo (x and weights) -------------------
__global__ void split_kernel(const float* __restrict__ A, int n4, int dest) {
    int i = blockIdx.x * blockDim.x + threadIdx.x;
    if (i >= n4) return;
    float4 v = ((const float4*)A)[i];
    __nv_bfloat162 h0, h1, l0, l1;
    split2(v.x, v.y, h0, l0);
    split2(v.z, v.w, h1, l1);
    __nv_bfloat162* dh = dest ? (__nv_bfloat162*)g_wh : (__nv_bfloat162*)g_ah;
    __nv_bfloat162* dl = dest ? (__nv_bfloat162*)g_wl : (__nv_bfloat162*)g_al;
    dh[i * 2] = h0; dh[i * 2 + 1] = h1;
    dl[i * 2] = l0; dl[i * 2 + 1] = l1;
}

// ---------------- tensor-core GEMM (256 thr, 64x32 warp tile, LDSM frags) -----
#define SP 24
#define SBYTES (128 * SP * 2)
__global__ __launch_bounds__(256, 2)
void gemm_tc_kernel(const float* __restrict__ bias, int c_id,
                    int Nout, int K, int doRelu, int in_sel, int out_mode) {
    const __nv_bfloat16* Ah = in_sel ? g_ah2 : g_ah;
    const __nv_bfloat16* Al = in_sel ? g_al2 : g_al;
    __shared__ __align__(16) __nv_bfloat16 sAh[2][128 * SP];
    __shared__ __align__(16) __nv_bfloat16 sAl[2][128 * SP];
    __shared__ __align__(16) __nv_bfloat16 sBh[2][128 * SP];
    __shared__ __align__(16) __nv_bfloat16 sBl[2][128 * SP];

    const int tid  = threadIdx.x;
    const int m0 = blockIdx.y * 128, n0 = blockIdx.x * 128;
    const int lrow = tid >> 1, lhalf = tid & 1;
    const size_t gA = (size_t)(m0 + lrow) * K + lhalf * 8;
    const size_t gB = (size_t)(n0 + lrow) * K + lhalf * 8;
    const int sofs = lrow * SP + lhalf * 8;

    const int w = tid >> 5, lane = tid & 31;
    const int wm = (w & 1) * 64, wn = (w >> 1) * 32;
    const int gr = lane >> 2, tg = lane & 3;

    // ldmatrix per-lane byte offsets (within a stage buffer)
    const unsigned aoff = (((lane & 15) * SP) + ((lane & 16) ? 8 : 0)) * 2;
    const unsigned boff = ((((lane & 7) + ((lane & 16) ? 8 : 0)) * SP) + ((lane & 8) ? 8 : 0)) * 2;
    const unsigned bAh = (unsigned)__cvta_generic_to_shared(&sAh[0][0]);
    const unsigned bAl = (unsigned)__cvta_generic_to_shared(&sAl[0][0]);
    const unsigned bBh = (unsigned)__cvta_generic_to_shared(&sBh[0][0]);
    const unsigned bBl = (unsigned)__cvta_generic_to_shared(&sBl[0][0]);

    float acc[4][4][4];
    #pragma unroll
    for (int mt = 0; mt < 4; mt++)
        #pragma unroll
        for (int nt = 0; nt < 4; nt++)
            #pragma unroll
            for (int r = 0; r < 4; r++) acc[mt][nt][r] = 0.f;

    cp_async16(&sAh[0][sofs], &Ah[gA]);
    cp_async16(&sAl[0][sofs], &Al[gA]);
    cp_async16(&sBh[0][sofs], &g_wh[gB]);
    cp_async16(&sBl[0][sofs], &g_wl[gB]);
    cp_commit(); cp_wait0();
    __syncthreads();

    const int T = K >> 4;
    for (int t = 0; t < T; t++) {
        const int cur = t & 1;
        if (t + 1 < T) {
            const int nxt = cur ^ 1;
            int kt = (t + 1) << 4;
            cp_async16(&sAh[nxt][sofs], &Ah[gA + kt]);
            cp_async16(&sAl[nxt][sofs], &Al[gA + kt]);
            cp_async16(&sBh[nxt][sofs], &g_wh[gB + kt]);
            cp_async16(&sBl[nxt][sofs], &g_wl[gB + kt]);
            cp_commit();
        }

        const unsigned stg = cur * SBYTES;
        unsigned ah[4][4], al[4][4], bh[4][2], bl[4][2];
        #pragma unroll
        for (int mt = 0; mt < 4; mt++) {
            unsigned rowo = (wm + mt * 16) * SP * 2;
            ldsm_x4(ah[mt], bAh + stg + rowo + aoff);
            ldsm_x4(al[mt], bAl + stg + rowo + aoff);
        }
        #pragma unroll
        for (int np = 0; np < 2; np++) {
            unsigned rowo = (wn + np * 16) * SP * 2;
            ldsm_x4(&bh[np * 2][0], bBh + stg + rowo + boff);
            ldsm_x4(&bl[np * 2][0], bBl + stg + rowo + boff);
        }
        #pragma unroll
        for (int mt = 0; mt < 4; mt++)
            #pragma unroll
            for (int nt = 0; nt < 4; nt++) {
                mma_bf16(acc[mt][nt], ah[mt], bh[nt]);
                mma_bf16(acc[mt][nt], ah[mt], bl[nt]);
                mma_bf16(acc[mt][nt], al[mt], bh[nt]);
            }

        if (t + 1 < T) cp_wait0();
        __syncthreads();
    }

    float* C = buf_ptr(c_id);
    #pragma unroll
    for (int mt = 0; mt < 4; mt++) {
        int row = m0 + wm + mt * 16 + gr;
        #pragma unroll
        for (int nt = 0; nt < 4; nt++) {
            int col = n0 + wn + nt * 8 + 2 * tg;
            float b0 = bias ? bias[col] : 0.f;
            float b1 = bias ? bias[col + 1] : 0.f;
            float o0 = acc[mt][nt][0] + b0, o1 = acc[mt][nt][1] + b1;
            float o2 = acc[mt][nt][2] + b0, o3 = acc[mt][nt][3] + b1;
            if (doRelu) {
                o0 = fmaxf(o0, 0.f); o1 = fmaxf(o1, 0.f);
                o2 = fmaxf(o2, 0.f); o3 = fmaxf(o3, 0.f);
            }
            if (out_mode == 0) {
                *(float2*)&C[(size_t)row * Nout + col]       = make_float2(o0, o1);
                *(float2*)&C[(size_t)(row + 8) * Nout + col] = make_float2(o2, o3);
            } else {
                __nv_bfloat162 h0, l0, h1, l1;
                split2(o0, o1, h0, l0);
                split2(o2, o3, h1, l1);
                *(__nv_bfloat162*)&g_ah2[(size_t)row * Nout + col]       = h0;
                *(__nv_bfloat162*)&g_al2[(size_t)row * Nout + col]       = l0;
                *(__nv_bfloat162*)&g_ah2[(size_t)(row + 8) * Nout + col] = h1;
                *(__nv_bfloat162*)&g_al2[(size_t)(row + 8) * Nout + col] = l1;
            }
        }
    }
}

// ---------------- edge_index dtype probe -------------------------------------
__global__ void detect_idx_kernel(const void* __restrict__ ei) {
    if (threadIdx.x == 0 && blockIdx.x == 0) {
        const long long* p = (const long long*)ei;
        int ok64 = 1;
        for (int i = 0; i < 256; i++) {
            long long v = p[i];
            if (v < 0 || v >= N_NODES) { ok64 = 0; break; }
        }
        g_is64 = ok64;
    }
}
__device__ __forceinline__ void edge_nodes(const void* __restrict__ ei, int e,
                                           int& src, int& dst) {
    if (g_is64) {
        const long long* p = (const long long*)ei;
        src = (int)p[e]; dst = (int)p[E_IN + e];
    } else {
        const int* p = (const int*)ei;
        src = p[e]; dst = p[E_IN + e];
    }
    src = min(max(src, 0), N_NODES - 1);
    dst = min(max(dst, 0), N_NODES - 1);
}

// ---------------- CSR build ---------------------------------------------------
__global__ void zero_deg_kernel() {
    int i = blockIdx.x * blockDim.x + threadIdx.x;
    if (i < N_NODES) g_deg[i] = 0;
}
__global__ void hist_kernel(const void* __restrict__ ei) {
    int e = blockIdx.x * blockDim.x + threadIdx.x;
    if (e >= E_IN) return;
    int src, dst; edge_nodes(ei, e, src, dst);
    atomicAdd(&g_deg[dst], 1);
}
__global__ __launch_bounds__(1024)
void scan_kernel() {
    __shared__ int wsum[32];
    int t = threadIdx.x;
    int base = t * 16;
    int4 d0 = *(const int4*)&g_deg[base + 0];
    int4 d1 = *(const int4*)&g_deg[base + 4];
    int4 d2 = *(const int4*)&g_deg[base + 8];
    int4 d3 = *(const int4*)&g_deg[base + 12];
    int v0 = d0.x, v1 = d0.y, v2 = d0.z, v3 = d0.w;
    int v4 = d1.x, v5 = d1.y, v6 = d1.z, v7 = d1.w;
    int v8 = d2.x, v9 = d2.y, v10 = d2.z, v11 = d2.w;
    int v12 = d3.x, v13 = d3.y, v14 = d3.z, v15 = d3.w;
    int l0=0, l1=v0, l2=l1+v1, l3=l2+v2, l4=l3+v3, l5=l4+v4, l6=l5+v5, l7=l6+v6,
        l8=l7+v7, l9=l8+v8, l10=l9+v9, l11=l10+v10, l12=l11+v11, l13=l12+v12,
        l14=l13+v13, l15=l14+v14;
    int s = l15 + v15;
    int lane = t & 31, warp = t >> 5;
    int inc = s;
    #pragma unroll
    for (int d = 1; d < 32; d <<= 1) {
        int v = __shfl_up_sync(0xffffffffu, inc, d);
        if (lane >= d) inc += v;
    }
    if (lane == 31) wsum[warp] = inc;
    __syncthreads();
    if (warp == 0) {
        int v = wsum[lane];
        #pragma unroll
        for (int d = 1; d < 32; d <<= 1) {
            int u = __shfl_up_sync(0xffffffffu, v, d);
            if (lane >= d) v += u;
        }
        wsum[lane] = v;
    }
    __syncthreads();
    int p = (warp ? wsum[warp - 1] : 0) + (inc - s);
    int4 o0 = make_int4(p+l0,  p+l1,  p+l2,  p+l3);
    int4 o1 = make_int4(p+l4,  p+l5,  p+l6,  p+l7);
    int4 o2 = make_int4(p+l8,  p+l9,  p+l10, p+l11);
    int4 o3 = make_int4(p+l12, p+l13, p+l14, p+l15);
    *(int4*)&g_off[base + 0]  = o0;  *(int4*)&g_off[base + 4]  = o1;
    *(int4*)&g_off[base + 8]  = o2;  *(int4*)&g_off[base + 12] = o3;
    *(int4*)&g_deg[base + 0]  = o0;  *(int4*)&g_deg[base + 4]  = o1;
    *(int4*)&g_deg[base + 8]  = o2;  *(int4*)&g_deg[base + 12] = o3;
    if (t == 1023) g_off[N_NODES] = E_IN;
}
__global__ void scatter_kernel(const void* __restrict__ ei) {
    int e = blockIdx.x * blockDim.x + threadIdx.x;
    if (e >= E_IN) return;
    int src, dst; edge_nodes(ei, e, src, dst);
    int pos = atomicAdd(&g_deg[dst], 1);
    g_csr_src[pos] = src;
}

// ---------------- small GEMM (Nout<128): 64x64 tile, 4x4 microtile -----------
__global__ __launch_bounds__(256)
void gemm_kernel(int a_id, const float* __restrict__ W, const float* __restrict__ bias,
                 int c_id, int Nout, int K, int doRelu) {
    const float* A = (const float*)buf_ptr(a_id);
    float* C = buf_ptr(c_id);

    __shared__ float As[16][64];
    __shared__ float Ws[16][64];
    const int tid = threadIdx.x;
    const int tx = tid & 15, ty = tid >> 4;
    const int m0 = blockIdx.y * 64;
    const int n0 = blockIdx.x * 64;
    const int lr = tid >> 2;
    const int lc = (tid & 3) * 4;

    float acc[4][4];
    #pragma unroll
    for (int i = 0; i < 4; i++)
        #pragma unroll
        for (int j = 0; j < 4; j++) acc[i][j] = 0.f;

    for (int kt = 0; kt < K; kt += 16) {
        float4 av = *(const float4*)&A[(size_t)(m0 + lr) * K + kt + lc];
        As[lc + 0][lr] = av.x; As[lc + 1][lr] = av.y;
        As[lc + 2][lr] = av.z; As[lc + 3][lr] = av.w;
        float4 wv = make_float4(0.f, 0.f, 0.f, 0.f);
        if (n0 + lr < Nout)
            wv = *(const float4*)&W[(size_t)(n0 + lr) * K + kt + lc];
        Ws[lc + 0][lr] = wv.x; Ws[lc + 1][lr] = wv.y;
        Ws[lc + 2][lr] = wv.z; Ws[lc + 3][lr] = wv.w;
        __syncthreads();
        #pragma unroll
        for (int k = 0; k < 16; k++) {
            float4 a = *(const float4*)&As[k][ty * 4];
            float4 b = *(const float4*)&Ws[k][tx * 4];
            acc[0][0] = fmaf(a.x, b.x, acc[0][0]); acc[0][1] = fmaf(a.x, b.y, acc[0][1]);
            acc[0][2] = fmaf(a.x, b.z, acc[0][2]); acc[0][3] = fmaf(a.x, b.w, acc[0][3]);
            acc[1][0] = fmaf(a.y, b.x, acc[1][0]); acc[1][1] = fmaf(a.y, b.y, acc[1][1]);
            acc[1][2] = fmaf(a.y, b.z, acc[1][2]); acc[1][3] = fmaf(a.y, b.w, acc[1][3]);
            acc[2][0] = fmaf(a.z, b.x, acc[2][0]); acc[2][1] = fmaf(a.z, b.y, acc[2][1]);
            acc[2][2] = fmaf(a.z, b.z, acc[2][2]); acc[2][3] = fmaf(a.z, b.w, acc[2][3]);
            acc[3][0] = fmaf(a.w, b.x, acc[3][0]); acc[3][1] = fmaf(a.w, b.y, acc[3][1]);
            acc[3][2] = fmaf(a.w, b.z, acc[3][2]); acc[3][3] = fmaf(a.w, b.w, acc[3][3]);
        }
        __syncthreads();
    }

    const int col = n0 + tx * 4;
    if (col < Nout) {
        float bx = bias[col], by = bias[col + 1], bz = bias[col + 2], bw = bias[col + 3];
        #pragma unroll
        for (int i = 0; i < 4; i++) {
            int row = m0 + ty * 4 + i;
            float4 v = make_float4(acc[i][0] + bx, acc[i][1] + by,
                                   acc[i][2] + bz, acc[i][3] + bw);
            if (doRelu) {
                v.x = fmaxf(v.x, 0.f); v.y = fmaxf(v.y, 0.f);
                v.z = fmaxf(v.z, 0.f); v.w = fmaxf(v.w, 0.f);
            }
            *(float4*)&C[(size_t)row * Nout + col] = v;
        }
    }
}

// ---------------- attention scores: warp per (node, head) --------------------
__global__ void attn_scores_kernel(const float* __restrict__ att_src,
                                   const float* __restrict__ att_dst) {
    int gw = (blockIdx.x * blockDim.x + threadIdx.x) >> 5;
    int lane = threadIdx.x & 31;
    if (gw >= N_NODES * HEADS) return;
    int node = gw >> 1, head = gw & 1;
    const float* hp = g_h + (size_t)node * F_DIM + head * OUT_CH + lane * 8;
    const float* sp = att_src + head * OUT_CH + lane * 8;
    const float* dp = att_dst + head * OUT_CH + lane * 8;
    float4 h0 = *(const float4*)hp,  h1 = *(const float4*)(hp + 4);
    float4 s0 = *(const float4*)sp,  s1 = *(const float4*)(sp + 4);
    float4 d0 = *(const float4*)dp,  d1 = *(const float4*)(dp + 4);
    float s = h0.x * s0.x + h0.y * s0.y + h0.z * s0.z + h0.w * s0.w
            + h1.x * s1.x + h1.y * s1.y + h1.z * s1.z + h1.w * s1.w;
    float d = h0.x * d0.x + h0.y * d0.y + h0.z * d0.z + h0.w * d0.w
            + h1.x * d1.x + h1.y * d1.y + h1.z * d1.z + h1.w * d1.w;
    #pragma unroll
    for (int o = 16; o; o >>= 1) {
        s += __shfl_xor_sync(0xffffffffu, s, o);
        d += __shfl_xor_sync(0xffffffffu, d, o);
    }
    if (lane == 0) { g_as[gw] = s; g_ad[gw] = d; }
}

// ---------------- fused GAT: softmax + aggregate + bias + relu + bf16 split --
__global__ __launch_bounds__(128)
void gat_agg_kernel(const float* __restrict__ conv_b) {
    const int dst = blockIdx.x;
    const int t = threadIdx.x;
    __shared__ float red[128];
    __shared__ float sh_a0[128], sh_a1[128];
    __shared__ int   sh_src[128];
    __shared__ float sm0, sm1, ss0, ss1;

    const int off = g_off[dst];
    const int deg = g_off[dst + 1] - off;
    const float ad0 = g_ad[dst * 2], ad1 = g_ad[dst * 2 + 1];
    const float self0 = lrelu(g_as[dst * 2] + ad0);
    const float self1 = lrelu(g_as[dst * 2 + 1] + ad1);

    float m0 = self0, m1 = self1;
    for (int j = t; j < deg; j += 128) {
        int s = g_csr_src[off + j];
        m0 = fmaxf(m0, lrelu(g_as[s * 2] + ad0));
        m1 = fmaxf(m1, lrelu(g_as[s * 2 + 1] + ad1));
    }
    red[t] = m0; __syncthreads();
    for (int d = 64; d; d >>= 1) { if (t < d) red[t] = fmaxf(red[t], red[t + d]); __syncthreads(); }
    if (t == 0) sm0 = red[0];
    __syncthreads();
    red[t] = m1; __syncthreads();
    for (int d = 64; d; d >>= 1) { if (t < d) red[t] = fmaxf(red[t], red[t + d]); __syncthreads(); }
    if (t == 0) sm1 = red[0];
    __syncthreads();
    m0 = sm0; m1 = sm1;

    float s0 = (t == 0) ? expf(self0 - m0) : 0.f;
    float s1 = (t == 0) ? expf(self1 - m1) : 0.f;
    for (int j = t; j < deg; j += 128) {
        int s = g_csr_src[off + j];
        s0 += expf(lrelu(g_as[s * 2] + ad0) - m0);
        s1 += expf(lrelu(g_as[s * 2 + 1] + ad1) - m1);
    }
    red[t] = s0; __syncthreads();
    for (int d = 64; d; d >>= 1) { if (t < d) red[t] += red[t + d]; __syncthreads(); }
    if (t == 0) ss0 = red[0];
    __syncthreads();
    red[t] = s1; __syncthreads();
    for (int d = 64; d; d >>= 1) { if (t < d) red[t] += red[t + d]; __syncthreads(); }
    if (t == 0) ss1 = red[0];
    __syncthreads();
    const float rs0 = 1.f / ss0, rs1 = 1.f / ss1;

    const int head = t >> 6;
    const float mself  = head ? self1 : self0;
    const float mmax   = head ? sm1 : sm0;
    const float rss    = head ? rs1 : rs0;
    const float a_self = expf(mself - mmax) * rss;

    float4 v = *(const float4*)&g_h[(size_t)dst * F_DIM + t * 4];
    float4 acc = make_float4(a_self * v.x, a_self * v.y, a_self * v.z, a_self * v.w);

    for (int c = 0; c < deg; c += 128) {
        int j = c + t;
        if (j < deg) {
            int s = g_csr_src[off + j];
            sh_src[t] = s;
            sh_a0[t] = expf(lrelu(g_as[s * 2] + ad0) - sm0) * rs0;
            sh_a1[t] = expf(lrelu(g_as[s * 2 + 1] + ad1) - sm1) * rs1;
        }
        __syncthreads();
        int cnt = min(128, deg - c);
        for (int j2 = 0; j2 < cnt; j2++) {
            const float4 hv = *(const float4*)&g_h[(size_t)sh_src[j2] * F_DIM + t * 4];
            float a = head ? sh_a1[j2] : sh_a0[j2];
            acc.x = fmaf(a, hv.x, acc.x);
            acc.y = fmaf(a, hv.y, acc.y);
            acc.z = fmaf(a, hv.z, acc.z);
            acc.w = fmaf(a, hv.w, acc.w);
        }
        __syncthreads();
    }

    float4 b = *(const float4*)&conv_b[t * 4];
    acc.x = fmaxf(acc.x + b.x, 0.f);
    acc.y = fmaxf(acc.y + b.y, 0.f);
    acc.z = fmaxf(acc.z + b.z, 0.f);
    acc.w = fmaxf(acc.w + b.w, 0.f);
    __nv_bfloat162 h0, l0, h1, l1;
    split2(acc.x, acc.y, h0, l0);
    split2(acc.z, acc.w, h1, l1);
    size_t idx = (size_t)dst * F_DIM + t * 4;
    *(__nv_bfloat162*)&g_ah[idx]     = h0;
    *(__nv_bfloat162*)&g_ah[idx + 2] = h1;
    *(__nv_bfloat162*)&g_al[idx]     = l0;
    *(__nv_bfloat162*)&g_al[idx + 2] = l1;
}

// ---------------- last MLP layer: 32 -> 3, also store |p|^2 -------------------
__global__ __launch_bounds__(256)
void final_layer_kernel(const float* __restrict__ W4, const float* __restrict__ b4) {
    __shared__ float w[3][32];
    __shared__ float bb[3];
    int tid = threadIdx.x;
    if (tid < 96) w[tid / 32][tid & 31] = W4[tid];
    if (tid < 3)  bb[tid] = b4[tid];
    __syncthreads();
    int n = blockIdx.x * blockDim.x + tid;
    if (n >= N_NODES) return;
    const float4* hp = (const float4*)(g_h4 + (size_t)n * 32);
    float a0 = bb[0], a1 = bb[1], a2 = bb[2];
    #pragma unroll
    for (int q = 0; q < 8; q++) {
        float4 v = hp[q];
        a0 = fmaf(v.x, w[0][q*4+0], a0); a0 = fmaf(v.y, w[0][q*4+1], a0);
        a0 = fmaf(v.z, w[0][q*4+2], a0); a0 = fmaf(v.w, w[0][q*4+3], a0);
        a1 = fmaf(v.x, w[1][q*4+0], a1); a1 = fmaf(v.y, w[1][q*4+1], a1);
        a1 = fmaf(v.z, w[1][q*4+2], a1); a1 = fmaf(v.w, w[1][q*4+3], a1);
        a2 = fmaf(v.x, w[2][q*4+0], a2); a2 = fmaf(v.y, w[2][q*4+1], a2);
        a2 = fmaf(v.z, w[2][q*4+2], a2); a2 = fmaf(v.w, w[2][q*4+3], a2);
    }
    float sq = fmaf(a0, a0, fmaf(a1, a1, a2 * a2));
    ((float4*)g_h5)[n] = make_float4(a0, a1, a2, sq);
}

// ---------------- pairwise distances: d2 = sp+sq-2*dot, MUFU rsqrt ------------
__global__ __launch_bounds__(256)
void cdist_kernel(float* __restrict__ out) {
    __shared__ float4 rp[128];
    __shared__ float4 cp[128];
    int tid = threadIdx.x;
    int rb = blockIdx.y * 128, cb = blockIdx.x * 128;
    if (tid < 128) rp[tid] = ((const float4*)g_h5)[rb + tid];
    else           cp[tid - 128] = ((const float4*)g_h5)[cb + tid - 128];
    __syncthreads();
    int tx = tid & 31, ty = tid >> 5;
    float4 q0 = cp[tx * 4 + 0], q1 = cp[tx * 4 + 1],
           q2 = cp[tx * 4 + 2], q3 = cp[tx * 4 + 3];
    #pragma unroll
    for (int j = 0; j < 16; j++) {
        int r = j * 8 + ty;
        float4 p = rp[r];
        float4 o;
        float t, d2;
        t = p.x * q0.x; t = fmaf(p.y, q0.y, t); t = fmaf(p.z, q0.z, t);
        d2 = fmaf(-2.f, t, p.w + q0.w); d2 = fmaxf(d2, 0.f);
        o.x = d2 * rsqrt_approx(fmaxf(d2, 1e-35f));
        t = p.x * q1.x; t = fmaf(p.y, q1.y, t); t = fmaf(p.z, q1.z, t);
        d2 = fmaf(-2.f, t, p.w + q1.w); d2 = fmaxf(d2, 0.f);
        o.y = d2 * rsqrt_approx(fmaxf(d2, 1e-35f));
        t = p.x * q2.x; t = fmaf(p.y, q2.y, t); t = fmaf(p.z, q2.z, t);
        d2 = fmaf(-2.f, t, p.w + q2.w); d2 = fmaxf(d2, 0.f);
        o.z = d2 * rsqrt_approx(fmaxf(d2, 1e-35f));
        t = p.x * q3.x; t = fmaf(p.y, q3.y, t); t = fmaf(p.z, q3.z, t);
        d2 = fmaf(-2.f, t, p.w + q3.w); d2 = fmaxf(d2, 0.f);
        o.w = d2 * rsqrt_approx(fmaxf(d2, 1e-35f));
        __stcs((float4*)&out[(size_t)(rb + r) * N_NODES + cb + tx * 4], o);
    }
}

// ---------------- launch -------------------------------------------------------
extern "C" void kernel_launch(void* const* d_in, const int* in_sizes, int n_in,
                              void* d_out, int out_size) {
    const float* x       = (const float*)d_in[0];
    const void*  ei      = (const void*)d_in[1];
    const float* conv_W  = (const float*)d_in[2];
    const float* att_src = (const float*)d_in[3];
    const float* att_dst = (const float*)d_in[4];
    const float* conv_b  = (const float*)d_in[5];
    const float* Wa = (const float*)d_in[6];  const float* ba = (const float*)d_in[7];
    const float* W1 = (const float*)d_in[8];  const float* b1 = (const float*)d_in[9];
    const float* W2 = (const float*)d_in[10]; const float* b2 = (const float*)d_in[11];
    const float* W3 = (const float*)d_in[12]; const float* b3 = (const float*)d_in[13];
    const float* W4 = (const float*)d_in[14]; const float* b4 = (const float*)d_in[15];
    float*       out = (float*)d_out;

    detect_idx_kernel<<<1, 32>>>(ei);                                        // 1
    split_kernel<<<(N_NODES * IN_DIM / 4 + 255) / 256, 256>>>(x, N_NODES * IN_DIM / 4, 0);      // 2
    split_kernel<<<(F_DIM * IN_DIM / 4 + 255) / 256, 256>>>(conv_W, F_DIM * IN_DIM / 4, 1);     // 3
    // conv GEMM: h = x @ conv_W^T  (launch #4, profiled)
    gemm_tc_kernel<<<dim3(F_DIM / 128, N_NODES / 128), 256>>>(nullptr, BUF_H, F_DIM, IN_DIM, 0, 0, 0);

    // CSR build
    zero_deg_kernel<<<(N_NODES + 255) / 256, 256>>>();
    hist_kernel<<<(E_IN + 255) / 256, 256>>>(ei);
    scan_kernel<<<1, 1024>>>();
    scatter_kernel<<<(E_IN + 255) / 256, 256>>>(ei);

    attn_scores_kernel<<<(N_NODES * HEADS * 32 + 255) / 256, 256>>>(att_src, att_dst);
    gat_agg_kernel<<<N_NODES, 128>>>(conv_b);   // writes bf16 split to g_ah/g_al

    // Wa: [N,512] -> [N,256]
    split_kernel<<<(256 * 512 / 4 + 255) / 256, 256>>>(Wa, 256 * 512 / 4, 1);
    gemm_tc_kernel<<<dim3(256 / 128, N_NODES / 128), 256>>>(ba, BUF_H, 256, 512, 1, 0, 1);

    // W1: [N,256] -> [N,128]
    split_kernel<<<(128 * 256 / 4 + 255) / 256, 256>>>(W1, 128 * 256 / 4, 1);
    gemm_tc_kernel<<<dim3(128 / 128, N_NODES / 128), 256>>>(b1, BUF_H2, 128, 256, 1, 1, 0);

    // small layers fp32 SIMT
    gemm_kernel<<<dim3(1, N_NODES / 64), 256>>>(BUF_H2, W2, b2, BUF_H3, 64, 128, 1);
    gemm_kernel<<<dim3(1, N_NODES / 64), 256>>>(BUF_H3, W3, b3, BUF_H4, 32, 64, 1);
    final_layer_kernel<<<N_NODES / 256, 256>>>(W4, b4);

    cdist_kernel<<<dim3(N_NODES / 128, N_NODES / 128), 256>>>(out);
}

// round 14
// speedup vs baseline: 1.1251x; 1.0005x over previous
#include <cuda_runtime.h>
#include <cuda_bf16.h>
#include <math.h>

#define N_NODES 16384
#define IN_DIM  256
#define HEADS   2
#define OUT_CH  256
#define F_DIM   512
#define E_IN    524288

// ---------------- scratch (device globals) ----------------------------------
__device__ float    g_h   [N_NODES * F_DIM];
__device__ float    g_as  [N_NODES * HEADS];
__device__ float    g_ad  [N_NODES * HEADS];
__device__ int      g_deg [N_NODES];
__device__ int      g_off [N_NODES + 1];
__device__ int      g_csr_src[E_IN];
__device__ float    g_h2  [N_NODES * 128];
__device__ float    g_h3  [N_NODES * 64];
__device__ float    g_h4  [N_NODES * 32];
__device__ float    g_h5  [N_NODES * 4];     // x,y,z,|p|^2
__device__ int      g_is64;
__device__ __nv_bfloat16 g_ah [N_NODES * F_DIM];
__device__ __nv_bfloat16 g_al [N_NODES * F_DIM];
__device__ __nv_bfloat16 g_ah2[N_NODES * 256];
__device__ __nv_bfloat16 g_al2[N_NODES * 256];
__device__ __nv_bfloat16 g_wh[512 * 256];
__device__ __nv_bfloat16 g_wl[512 * 256];

#define BUF_H   0
#define BUF_H2  3
#define BUF_H3  4
#define BUF_H4  5
__device__ __forceinline__ float* buf_ptr(int id) {
    switch (id) {
        case BUF_H:   return g_h;
        case BUF_H2:  return g_h2;
        case BUF_H3:  return g_h3;
        default:      return g_h4;
    }
}

// ---------------- helpers ---------------------------------------------------
__device__ __forceinline__ float lrelu(float v) { return v > 0.f ? v : 0.2f * v; }

__device__ __forceinline__ float rsqrt_approx(float x) {
    float r;
    asm("rsqrt.approx.f32 %0, %1;" : "=f"(r) : "f"(x));
    return r;
}

__device__ __forceinline__ void mma_bf16(float* c, const unsigned* a, const unsigned* b) {
    asm volatile(
        "mma.sync.aligned.m16n8k16.row.col.f32.bf16.bf16.f32 "
        "{%0,%1,%2,%3}, {%4,%5,%6,%7}, {%8,%9}, {%0,%1,%2,%3};"
        : "+f"(c[0]), "+f"(c[1]), "+f"(c[2]), "+f"(c[3])
        : "r"(a[0]), "r"(a[1]), "r"(a[2]), "r"(a[3]), "r"(b[0]), "r"(b[1]));
}

__device__ __forceinline__ void ldsm_x4(unsigned* r, unsigned saddr) {
    asm volatile("ldmatrix.sync.aligned.m8n8.x4.shared.b16 {%0,%1,%2,%3}, [%4];"
        : "=r"(r[0]), "=r"(r[1]), "=r"(r[2]), "=r"(r[3]) : "r"(saddr));
}

__device__ __forceinline__ void cp_async16s(unsigned smem_dst, const void* gsrc) {
    asm volatile("cp.async.ca.shared.global [%0], [%1], 16;" :: "r"(smem_dst), "l"(gsrc));
}
__device__ __forceinline__ void cp_commit() { asm volatile("cp.async.commit_group;"); }
template <int N>
__device__ __forceinline__ void cp_wait() {
    asm volatile("cp.async.wait_group %0;" :: "n"(N) : "memory");
}

__device__ __forceinline__ void split2(float a, float b, __nv_bfloat162& h, __nv_bfloat162& l) {
    __nv_bfloat16 ha = __float2bfloat16_rn(a);
    __nv_bfloat16 hb = __float2bfloat16_rn(b);
    h.x = ha; h.y = hb;
    l.x = __float2bfloat16_rn(a - __bfloat162float(ha));
    l.y = __float2bfloat16_rn(b - __bfloat162float(hb));
}

// ---------------- split fp32 -> bf16 hi/lo (x and weights) -------------------
__global__ void split_kernel(const float* __restrict__ A, int n4, int dest) {
    int i = blockIdx.x * blockDim.x + threadIdx.x;
    if (i >= n4) return;
    float4 v = ((const float4*)A)[i];
    __nv_bfloat162 h0, h1, l0, l1;
    split2(v.x, v.y, h0, l0);
    split2(v.z, v.w, h1, l1);
    __nv_bfloat162* dh = dest ? (__nv_bfloat162*)g_wh : (__nv_bfloat162*)g_ah;
    __nv_bfloat162* dl = dest ? (__nv_bfloat162*)g_wl : (__nv_bfloat162*)g_al;
    dh[i * 2] = h0; dh[i * 2 + 1] = h1;
    dl[i * 2] = l0; dl[i * 2 + 1] = l1;
}

// ---------------- tensor-core GEMM (256 thr, 64x32 warp tile, LDSM, 3-stage) --
#define SP 24
#define OPB  6144                 // bytes per operand tile (128 * SP * 2)
#define STGB (4 * OPB)            // stage bytes (Ah, Al, Bh, Bl)
#define NSTG 3
__global__ __launch_bounds__(256, 2)
void gemm_tc_kernel(const float* __restrict__ bias, int c_id,
                    int Nout, int K, int doRelu, int in_sel, int out_mode) {
    extern __shared__ __align__(16) char dsm[];
    const __nv_bfloat16* Ah = in_sel ? g_ah2 : g_ah;
    const __nv_bfloat16* Al = in_sel ? g_al2 : g_al;

    const unsigned sbase = (unsigned)__cvta_generic_to_shared(dsm);
    const int tid  = threadIdx.x;
    const int m0 = blockIdx.y * 128, n0 = blockIdx.x * 128;
    const int lrow = tid >> 1, lhalf = tid & 1;
    const size_t gA = (size_t)(m0 + lrow) * K + lhalf * 8;
    const size_t gB = (size_t)(n0 + lrow) * K + lhalf * 8;
    const unsigned sofs = (lrow * SP + lhalf * 8) * 2;   // bytes

    const int w = tid >> 5, lane = tid & 31;
    const int wm = (w & 1) * 64, wn = (w >> 1) * 32;
    const int gr = lane >> 2, tg = lane & 3;

    const unsigned aoff = (((lane & 15) * SP) + ((lane & 16) ? 8 : 0)) * 2;
    const unsigned boff = ((((lane & 7) + ((lane & 16) ? 8 : 0)) * SP) + ((lane & 8) ? 8 : 0)) * 2;

    float acc[4][4][4];
    #pragma unroll
    for (int mt = 0; mt < 4; mt++)
        #pragma unroll
        for (int nt = 0; nt < 4; nt++)
            #pragma unroll
            for (int r = 0; r < 4; r++) acc[mt][nt][r] = 0.f;

    const int T = K >> 4;
    // preload stages 0 and 1
    #pragma unroll
    for (int s = 0; s < 2; s++) {
        if (s < T) {
            unsigned sb = sbase + s * STGB;
            int kt = s << 4;
            cp_async16s(sb + 0 * OPB + sofs, &Ah[gA + kt]);
            cp_async16s(sb + 1 * OPB + sofs, &Al[gA + kt]);
            cp_async16s(sb + 2 * OPB + sofs, &g_wh[gB + kt]);
            cp_async16s(sb + 3 * OPB + sofs, &g_wl[gB + kt]);
            cp_commit();
        }
    }

    for (int t = 0; t < T; t++) {
        if (t + 2 < T) {
            unsigned sb = sbase + ((t + 2) % NSTG) * STGB;
            int kt = (t + 2) << 4;
            cp_async16s(sb + 0 * OPB + sofs, &Ah[gA + kt]);
            cp_async16s(sb + 1 * OPB + sofs, &Al[gA + kt]);
            cp_async16s(sb + 2 * OPB + sofs, &g_wh[gB + kt]);
            cp_async16s(sb + 3 * OPB + sofs, &g_wl[gB + kt]);
            cp_commit();
            cp_wait<2>();
        } else if (t + 2 == T) {
            cp_wait<1>();
        } else {
            cp_wait<0>();
        }
        __syncthreads();

        const unsigned stg = sbase + (t % NSTG) * STGB;
        unsigned ah[4][4], al[4][4], bh[4][2], bl[4][2];
        #pragma unroll
        for (int mt = 0; mt < 4; mt++) {
            unsigned rowo = (wm + mt * 16) * SP * 2;
            ldsm_x4(ah[mt], stg + 0 * OPB + rowo + aoff);
            ldsm_x4(al[mt], stg + 1 * OPB + rowo + aoff);
        }
        #pragma unroll
        for (int np = 0; np < 2; np++) {
            unsigned rowo = (wn + np * 16) * SP * 2;
            ldsm_x4(&bh[np * 2][0], stg + 2 * OPB + rowo + boff);
            ldsm_x4(&bl[np * 2][0], stg + 3 * OPB + rowo + boff);
        }
        #pragma unroll
        for (int mt = 0; mt < 4; mt++)
            #pragma unroll
            for (int nt = 0; nt < 4; nt++) {
                mma_bf16(acc[mt][nt], ah[mt], bh[nt]);
                mma_bf16(acc[mt][nt], ah[mt], bl[nt]);
                mma_bf16(acc[mt][nt], al[mt], bh[nt]);
            }
        __syncthreads();
    }

    float* C = buf_ptr(c_id);
    #pragma unroll
    for (int mt = 0; mt < 4; mt++) {
        int row = m0 + wm + mt * 16 + gr;
        #pragma unroll
        for (int nt = 0; nt < 4; nt++) {
            int col = n0 + wn + nt * 8 + 2 * tg;
            float b0 = bias ? bias[col] : 0.f;
            float b1 = bias ? bias[col + 1] : 0.f;
            float o0 = acc[mt][nt][0] + b0, o1 = acc[mt][nt][1] + b1;
            float o2 = acc[mt][nt][2] + b0, o3 = acc[mt][nt][3] + b1;
            if (doRelu) {
                o0 = fmaxf(o0, 0.f); o1 = fmaxf(o1, 0.f);
                o2 = fmaxf(o2, 0.f); o3 = fmaxf(o3, 0.f);
            }
            if (out_mode == 0) {
                *(float2*)&C[(size_t)row * Nout + col]       = make_float2(o0, o1);
                *(float2*)&C[(size_t)(row + 8) * Nout + col] = make_float2(o2, o3);
            } else {
                __nv_bfloat162 h0, l0, h1, l1;
                split2(o0, o1, h0, l0);
                split2(o2, o3, h1, l1);
                *(__nv_bfloat162*)&g_ah2[(size_t)row * Nout + col]       = h0;
                *(__nv_bfloat162*)&g_al2[(size_t)row * Nout + col]       = l0;
                *(__nv_bfloat162*)&g_ah2[(size_t)(row + 8) * Nout + col] = h1;
                *(__nv_bfloat162*)&g_al2[(size_t)(row + 8) * Nout + col] = l1;
            }
        }
    }
}

// ---------------- edge_index dtype probe -------------------------------------
__global__ void detect_idx_kernel(const void* __restrict__ ei) {
    if (threadIdx.x == 0 && blockIdx.x == 0) {
        const long long* p = (const long long*)ei;
        int ok64 = 1;
        for (int i = 0; i < 256; i++) {
            long long v = p[i];
            if (v < 0 || v >= N_NODES) { ok64 = 0; break; }
        }
        g_is64 = ok64;
    }
}
__device__ __forceinline__ void edge_nodes(const void* __restrict__ ei, int e,
                                           int& src, int& dst) {
    if (g_is64) {
        const long long* p = (const long long*)ei;
        src = (int)p[e]; dst = (int)p[E_IN + e];
    } else {
        const int* p = (const int*)ei;
        src = p[e]; dst = p[E_IN + e];
    }
    src = min(max(src, 0), N_NODES - 1);
    dst = min(max(dst, 0), N_NODES - 1);
}

// ---------------- CSR build ---------------------------------------------------
__global__ void zero_deg_kernel() {
    int i = blockIdx.x * blockDim.x + threadIdx.x;
    if (i < N_NODES) g_deg[i] = 0;
}
__global__ void hist_kernel(const void* __restrict__ ei) {
    int e = blockIdx.x * blockDim.x + threadIdx.x;
    if (e >= E_IN) return;
    int src, dst; edge_nodes(ei, e, src, dst);
    atomicAdd(&g_deg[dst], 1);
}
__global__ __launch_bounds__(1024)
void scan_kernel() {
    __shared__ int wsum[32];
    int t = threadIdx.x;
    int base = t * 16;
    int4 d0 = *(const int4*)&g_deg[base + 0];
    int4 d1 = *(const int4*)&g_deg[base + 4];
    int4 d2 = *(const int4*)&g_deg[base + 8];
    int4 d3 = *(const int4*)&g_deg[base + 12];
    int v0 = d0.x, v1 = d0.y, v2 = d0.z, v3 = d0.w;
    int v4 = d1.x, v5 = d1.y, v6 = d1.z, v7 = d1.w;
    int v8 = d2.x, v9 = d2.y, v10 = d2.z, v11 = d2.w;
    int v12 = d3.x, v13 = d3.y, v14 = d3.z, v15 = d3.w;
    int l0=0, l1=v0, l2=l1+v1, l3=l2+v2, l4=l3+v3, l5=l4+v4, l6=l5+v5, l7=l6+v6,
        l8=l7+v7, l9=l8+v8, l10=l9+v9, l11=l10+v10, l12=l11+v11, l13=l12+v12,
        l14=l13+v13, l15=l14+v14;
    int s = l15 + v15;
    int lane = t & 31, warp = t >> 5;
    int inc = s;
    #pragma unroll
    for (int d = 1; d < 32; d <<= 1) {
        int v = __shfl_up_sync(0xffffffffu, inc, d);
        if (lane >= d) inc += v;
    }
    if (lane == 31) wsum[warp] = inc;
    __syncthreads();
    if (warp == 0) {
        int v = wsum[lane];
        #pragma unroll
        for (int d = 1; d < 32; d <<= 1) {
            int u = __shfl_up_sync(0xffffffffu, v, d);
            if (lane >= d) v += u;
        }
        wsum[lane] = v;
    }
    __syncthreads();
    int p = (warp ? wsum[warp - 1] : 0) + (inc - s);
    int4 o0 = make_int4(p+l0,  p+l1,  p+l2,  p+l3);
    int4 o1 = make_int4(p+l4,  p+l5,  p+l6,  p+l7);
    int4 o2 = make_int4(p+l8,  p+l9,  p+l10, p+l11);
    int4 o3 = make_int4(p+l12, p+l13, p+l14, p+l15);
    *(int4*)&g_off[base + 0]  = o0;  *(int4*)&g_off[base + 4]  = o1;
    *(int4*)&g_off[base + 8]  = o2;  *(int4*)&g_off[base + 12] = o3;
    *(int4*)&g_deg[base + 0]  = o0;  *(int4*)&g_deg[base + 4]  = o1;
    *(int4*)&g_deg[base + 8]  = o2;  *(int4*)&g_deg[base + 12] = o3;
    if (t == 1023) g_off[N_NODES] = E_IN;
}
__global__ void scatter_kernel(const void* __restrict__ ei) {
    int e = blockIdx.x * blockDim.x + threadIdx.x;
    if (e >= E_IN) return;
    int src, dst; edge_nodes(ei, e, src, dst);
    int pos = atomicAdd(&g_deg[dst], 1);
    g_csr_src[pos] = src;
}

// ---------------- small GEMM (Nout<128): 64x64 tile, 4x4 microtile -----------
__global__ __launch_bounds__(256)
void gemm_kernel(int a_id, const float* __restrict__ W, const float* __restrict__ bias,
                 int c_id, int Nout, int K, int doRelu) {
    const float* A = (const float*)buf_ptr(a_id);
    float* C = buf_ptr(c_id);

    __shared__ float As[16][64];
    __shared__ float Ws[16][64];
    const int tid = threadIdx.x;
    const int tx = tid & 15, ty = tid >> 4;
    const int m0 = blockIdx.y * 64;
    const int n0 = blockIdx.x * 64;
    const int lr = tid >> 2;
    const int lc = (tid & 3) * 4;

    float acc[4][4];
    #pragma unroll
    for (int i = 0; i < 4; i++)
        #pragma unroll
        for (int j = 0; j < 4; j++) acc[i][j] = 0.f;

    for (int kt = 0; kt < K; kt += 16) {
        float4 av = *(const float4*)&A[(size_t)(m0 + lr) * K + kt + lc];
        As[lc + 0][lr] = av.x; As[lc + 1][lr] = av.y;
        As[lc + 2][lr] = av.z; As[lc + 3][lr] = av.w;
        float4 wv = make_float4(0.f, 0.f, 0.f, 0.f);
        if (n0 + lr < Nout)
            wv = *(const float4*)&W[(size_t)(n0 + lr) * K + kt + lc];
        Ws[lc + 0][lr] = wv.x; Ws[lc + 1][lr] = wv.y;
        Ws[lc + 2][lr] = wv.z; Ws[lc + 3][lr] = wv.w;
        __syncthreads();
        #pragma unroll
        for (int k = 0; k < 16; k++) {
            float4 a = *(const float4*)&As[k][ty * 4];
            float4 b = *(const float4*)&Ws[k][tx * 4];
            acc[0][0] = fmaf(a.x, b.x, acc[0][0]); acc[0][1] = fmaf(a.x, b.y, acc[0][1]);
            acc[0][2] = fmaf(a.x, b.z, acc[0][2]); acc[0][3] = fmaf(a.x, b.w, acc[0][3]);
            acc[1][0] = fmaf(a.y, b.x, acc[1][0]); acc[1][1] = fmaf(a.y, b.y, acc[1][1]);
            acc[1][2] = fmaf(a.y, b.z, acc[1][2]); acc[1][3] = fmaf(a.y, b.w, acc[1][3]);
            acc[2][0] = fmaf(a.z, b.x, acc[2][0]); acc[2][1] = fmaf(a.z, b.y, acc[2][1]);
            acc[2][2] = fmaf(a.z, b.z, acc[2][2]); acc[2][3] = fmaf(a.z, b.w, acc[2][3]);
            acc[3][0] = fmaf(a.w, b.x, acc[3][0]); acc[3][1] = fmaf(a.w, b.y, acc[3][1]);
            acc[3][2] = fmaf(a.w, b.z, acc[3][2]); acc[3][3] = fmaf(a.w, b.w, acc[3][3]);
        }
        __syncthreads();
    }

    const int col = n0 + tx * 4;
    if (col < Nout) {
        float bx = bias[col], by = bias[col + 1], bz = bias[col + 2], bw = bias[col + 3];
        #pragma unroll
        for (int i = 0; i < 4; i++) {
            int row = m0 + ty * 4 + i;
            float4 v = make_float4(acc[i][0] + bx, acc[i][1] + by,
                                   acc[i][2] + bz, acc[i][3] + bw);
            if (doRelu) {
                v.x = fmaxf(v.x, 0.f); v.y = fmaxf(v.y, 0.f);
                v.z = fmaxf(v.z, 0.f); v.w = fmaxf(v.w, 0.f);
            }
            *(float4*)&C[(size_t)row * Nout + col] = v;
        }
    }
}

// ---------------- attention scores: warp per (node, head) --------------------
__global__ void attn_scores_kernel(const float* __restrict__ att_src,
                                   const float* __restrict__ att_dst) {
    int gw = (blockIdx.x * blockDim.x + threadIdx.x) >> 5;
    int lane = threadIdx.x & 31;
    if (gw >= N_NODES * HEADS) return;
    int node = gw >> 1, head = gw & 1;
    const float* hp = g_h + (size_t)node * F_DIM + head * OUT_CH + lane * 8;
    const float* sp = att_src + head * OUT_CH + lane * 8;
    const float* dp = att_dst + head * OUT_CH + lane * 8;
    float4 h0 = *(const float4*)hp,  h1 = *(const float4*)(hp + 4);
    float4 s0 = *(const float4*)sp,  s1 = *(const float4*)(sp + 4);
    float4 d0 = *(const float4*)dp,  d1 = *(const float4*)(dp + 4);
    float s = h0.x * s0.x + h0.y * s0.y + h0.z * s0.z + h0.w * s0.w
            + h1.x * s1.x + h1.y * s1.y + h1.z * s1.z + h1.w * s1.w;
    float d = h0.x * d0.x + h0.y * d0.y + h0.z * d0.z + h0.w * d0.w
            + h1.x * d1.x + h1.y * d1.y + h1.z * d1.z + h1.w * d1.w;
    #pragma unroll
    for (int o = 16; o; o >>= 1) {
        s += __shfl_xor_sync(0xffffffffu, s, o);
        d += __shfl_xor_sync(0xffffffffu, d, o);
    }
    if (lane == 0) { g_as[gw] = s; g_ad[gw] = d; }
}

// ---------------- fused GAT: softmax + aggregate + bias + relu + bf16 split --
__global__ __launch_bounds__(128)
void gat_agg_kernel(const float* __restrict__ conv_b) {
    const int dst = blockIdx.x;
    const int t = threadIdx.x;
    __shared__ float red[128];
    __shared__ float sh_a0[128], sh_a1[128];
    __shared__ int   sh_src[128];
    __shared__ float sm0, sm1, ss0, ss1;

    const int off = g_off[dst];
    const int deg = g_off[dst + 1] - off;
    const float ad0 = g_ad[dst * 2], ad1 = g_ad[dst * 2 + 1];
    const float self0 = lrelu(g_as[dst * 2] + ad0);
    const float self1 = lrelu(g_as[dst * 2 + 1] + ad1);

    float m0 = self0, m1 = self1;
    for (int j = t; j < deg; j += 128) {
        int s = g_csr_src[off + j];
        m0 = fmaxf(m0, lrelu(g_as[s * 2] + ad0));
        m1 = fmaxf(m1, lrelu(g_as[s * 2 + 1] + ad1));
    }
    red[t] = m0; __syncthreads();
    for (int d = 64; d; d >>= 1) { if (t < d) red[t] = fmaxf(red[t], red[t + d]); __syncthreads(); }
    if (t == 0) sm0 = red[0];
    __syncthreads();
    red[t] = m1; __syncthreads();
    for (int d = 64; d; d >>= 1) { if (t < d) red[t] = fmaxf(red[t], red[t + d]); __syncthreads(); }
    if (t == 0) sm1 = red[0];
    __syncthreads();
    m0 = sm0; m1 = sm1;

    float s0 = (t == 0) ? expf(self0 - m0) : 0.f;
    float s1 = (t == 0) ? expf(self1 - m1) : 0.f;
    for (int j = t; j < deg; j += 128) {
        int s = g_csr_src[off + j];
        s0 += expf(lrelu(g_as[s * 2] + ad0) - m0);
        s1 += expf(lrelu(g_as[s * 2 + 1] + ad1) - m1);
    }
    red[t] = s0; __syncthreads();
    for (int d = 64; d; d >>= 1) { if (t < d) red[t] += red[t + d]; __syncthreads(); }
    if (t == 0) ss0 = red[0];
    __syncthreads();
    red[t] = s1; __syncthreads();
    for (int d = 64; d; d >>= 1) { if (t < d) red[t] += red[t + d]; __syncthreads(); }
    if (t == 0) ss1 = red[0];
    __syncthreads();
    const float rs0 = 1.f / ss0, rs1 = 1.f / ss1;

    const int head = t >> 6;
    const float mself  = head ? self1 : self0;
    const float mmax   = head ? sm1 : sm0;
    const float rss    = head ? rs1 : rs0;
    const float a_self = expf(mself - mmax) * rss;

    float4 v = *(const float4*)&g_h[(size_t)dst * F_DIM + t * 4];
    float4 acc = make_float4(a_self * v.x, a_self * v.y, a_self * v.z, a_self * v.w);

    for (int c = 0; c < deg; c += 128) {
        int j = c + t;
        if (j < deg) {
            int s = g_csr_src[off + j];
            sh_src[t] = s;
            sh_a0[t] = expf(lrelu(g_as[s * 2] + ad0) - sm0) * rs0;
            sh_a1[t] = expf(lrelu(g_as[s * 2 + 1] + ad1) - sm1) * rs1;
        }
        __syncthreads();
        int cnt = min(128, deg - c);
        for (int j2 = 0; j2 < cnt; j2++) {
            const float4 hv = *(const float4*)&g_h[(size_t)sh_src[j2] * F_DIM + t * 4];
            float a = head ? sh_a1[j2] : sh_a0[j2];
            acc.x = fmaf(a, hv.x, acc.x);
            acc.y = fmaf(a, hv.y, acc.y);
            acc.z = fmaf(a, hv.z, acc.z);
            acc.w = fmaf(a, hv.w, acc.w);
        }
        __syncthreads();
    }

    float4 b = *(const float4*)&conv_b[t * 4];
    acc.x = fmaxf(acc.x + b.x, 0.f);
    acc.y = fmaxf(acc.y + b.y, 0.f);
    acc.z = fmaxf(acc.z + b.z, 0.f);
    acc.w = fmaxf(acc.w + b.w, 0.f);
    __nv_bfloat162 h0, l0, h1, l1;
    split2(acc.x, acc.y, h0, l0);
    split2(acc.z, acc.w, h1, l1);
    size_t idx = (size_t)dst * F_DIM + t * 4;
    *(__nv_bfloat162*)&g_ah[idx]     = h0;
    *(__nv_bfloat162*)&g_ah[idx + 2] = h1;
    *(__nv_bfloat162*)&g_al[idx]     = l0;
    *(__nv_bfloat162*)&g_al[idx + 2] = l1;
}

// ---------------- last MLP layer: 32 -> 3, also store |p|^2 -------------------
__global__ __launch_bounds__(256)
void final_layer_kernel(const float* __restrict__ W4, const float* __restrict__ b4) {
    __shared__ float w[3][32];
    __shared__ float bb[3];
    int tid = threadIdx.x;
    if (tid < 96) w[tid / 32][tid & 31] = W4[tid];
    if (tid < 3)  bb[tid] = b4[tid];
    __syncthreads();
    int n = blockIdx.x * blockDim.x + tid;
    if (n >= N_NODES) return;
    const float4* hp = (const float4*)(g_h4 + (size_t)n * 32);
    float a0 = bb[0], a1 = bb[1], a2 = bb[2];
    #pragma unroll
    for (int q = 0; q < 8; q++) {
        float4 v = hp[q];
        a0 = fmaf(v.x, w[0][q*4+0], a0); a0 = fmaf(v.y, w[0][q*4+1], a0);
        a0 = fmaf(v.z, w[0][q*4+2], a0); a0 = fmaf(v.w, w[0][q*4+3], a0);
        a1 = fmaf(v.x, w[1][q*4+0], a1); a1 = fmaf(v.y, w[1][q*4+1], a1);
        a1 = fmaf(v.z, w[1][q*4+2], a1); a1 = fmaf(v.w, w[1][q*4+3], a1);
        a2 = fmaf(v.x, w[2][q*4+0], a2); a2 = fmaf(v.y, w[2][q*4+1], a2);
        a2 = fmaf(v.z, w[2][q*4+2], a2); a2 = fmaf(v.w, w[2][q*4+3], a2);
    }
    float sq = fmaf(a0, a0, fmaf(a1, a1, a2 * a2));
    ((float4*)g_h5)[n] = make_float4(a0, a1, a2, sq);
}

// ---------------- pairwise distances: d2 = sp+sq-2*dot, MUFU rsqrt ------------
__global__ __launch_bounds__(256)
void cdist_kernel(float* __restrict__ out) {
    __shared__ float4 rp[128];
    __shared__ float4 cp[128];
    int tid = threadIdx.x;
    int rb = blockIdx.y * 128, cb = blockIdx.x * 128;
    if (tid < 128) rp[tid] = ((const float4*)g_h5)[rb + tid];
    else           cp[tid - 128] = ((const float4*)g_h5)[cb + tid - 128];
    __syncthreads();
    int tx = tid & 31, ty = tid >> 5;
    float4 q0 = cp[tx * 4 + 0], q1 = cp[tx * 4 + 1],
           q2 = cp[tx * 4 + 2], q3 = cp[tx * 4 + 3];
    #pragma unroll
    for (int j = 0; j < 16; j++) {
        int r = j * 8 + ty;
        float4 p = rp[r];
        float4 o;
        float t, d2;
        t = p.x * q0.x; t = fmaf(p.y, q0.y, t); t = fmaf(p.z, q0.z, t);
        d2 = fmaf(-2.f, t, p.w + q0.w); d2 = fmaxf(d2, 0.f);
        o.x = d2 * rsqrt_approx(fmaxf(d2, 1e-35f));
        t = p.x * q1.x; t = fmaf(p.y, q1.y, t); t = fmaf(p.z, q1.z, t);
        d2 = fmaf(-2.f, t, p.w + q1.w); d2 = fmaxf(d2, 0.f);
        o.y = d2 * rsqrt_approx(fmaxf(d2, 1e-35f));
        t = p.x * q2.x; t = fmaf(p.y, q2.y, t); t = fmaf(p.z, q2.z, t);
        d2 = fmaf(-2.f, t, p.w + q2.w); d2 = fmaxf(d2, 0.f);
        o.z = d2 * rsqrt_approx(fmaxf(d2, 1e-35f));
        t = p.x * q3.x; t = fmaf(p.y, q3.y, t); t = fmaf(p.z, q3.z, t);
        d2 = fmaf(-2.f, t, p.w + q3.w); d2 = fmaxf(d2, 0.f);
        o.w = d2 * rsqrt_approx(fmaxf(d2, 1e-35f));
        __stcs((float4*)&out[(size_t)(rb + r) * N_NODES + cb + tx * 4], o);
    }
}

// ---------------- launch -------------------------------------------------------
extern "C" void kernel_launch(void* const* d_in, const int* in_sizes, int n_in,
                              void* d_out, int out_size) {
    const float* x       = (const float*)d_in[0];
    const void*  ei      = (const void*)d_in[1];
    const float* conv_W  = (const float*)d_in[2];
    const float* att_src = (const float*)d_in[3];
    const float* att_dst = (const float*)d_in[4];
    const float* conv_b  = (const float*)d_in[5];
    const float* Wa = (const float*)d_in[6];  const float* ba = (const float*)d_in[7];
    const float* W1 = (const float*)d_in[8];  const float* b1 = (const float*)d_in[9];
    const float* W2 = (const float*)d_in[10]; const float* b2 = (const float*)d_in[11];
    const float* W3 = (const float*)d_in[12]; const float* b3 = (const float*)d_in[13];
    const float* W4 = (const float*)d_in[14]; const float* b4 = (const float*)d_in[15];
    float*       out = (float*)d_out;

    const int TCSMEM = NSTG * STGB;   // 73728 bytes
    cudaFuncSetAttribute(gemm_tc_kernel,
                         cudaFuncAttributeMaxDynamicSharedMemorySize, TCSMEM);

    detect_idx_kernel<<<1, 32>>>(ei);                                        // 1
    split_kernel<<<(N_NODES * IN_DIM / 4 + 255) / 256, 256>>>(x, N_NODES * IN_DIM / 4, 0);      // 2
    split_kernel<<<(F_DIM * IN_DIM / 4 + 255) / 256, 256>>>(conv_W, F_DIM * IN_DIM / 4, 1);     // 3
    // conv GEMM: h = x @ conv_W^T  (launch #4, profiled)
    gemm_tc_kernel<<<dim3(F_DIM / 128, N_NODES / 128), 256, TCSMEM>>>(
        nullptr, BUF_H, F_DIM, IN_DIM, 0, 0, 0);

    // CSR build
    zero_deg_kernel<<<(N_NODES + 255) / 256, 256>>>();
    hist_kernel<<<(E_IN + 255) / 256, 256>>>(ei);
    scan_kernel<<<1, 1024>>>();
    scatter_kernel<<<(E_IN + 255) / 256, 256>>>(ei);

    attn_scores_kernel<<<(N_NODES * HEADS * 32 + 255) / 256, 256>>>(att_src, att_dst);
    gat_agg_kernel<<<N_NODES, 128>>>(conv_b);   // writes bf16 split to g_ah/g_al

    // Wa: [N,512] -> [N,256]
    split_kernel<<<(256 * 512 / 4 + 255) / 256, 256>>>(Wa, 256 * 512 / 4, 1);
    gemm_tc_kernel<<<dim3(256 / 128, N_NODES / 128), 256, TCSMEM>>>(
        ba, BUF_H, 256, 512, 1, 0, 1);

    // W1: [N,256] -> [N,128]
    split_kernel<<<(128 * 256 / 4 + 255) / 256, 256>>>(W1, 128 * 256 / 4, 1);
    gemm_tc_kernel<<<dim3(128 / 128, N_NODES / 128), 256, TCSMEM>>>(
        b1, BUF_H2, 128, 256, 1, 1, 0);

    // small layers fp32 SIMT
    gemm_kernel<<<dim3(1, N_NODES / 64), 256>>>(BUF_H2, W2, b2, BUF_H3, 64, 128, 1);
    gemm_kernel<<<dim3(1, N_NODES / 64), 256>>>(BUF_H3, W3, b3, BUF_H4, 32, 64, 1);
    final_layer_kernel<<<N_NODES / 256, 256>>>(W4, b4);

    cdist_kernel<<<dim3(N_NODES / 128, N_NODES / 128), 256>>>(out);
}

// round 15
// speedup vs baseline: 1.1251x; 1.0001x over previous
#include <cuda_runtime.h>
#include <cuda_bf16.h>
#include <math.h>

#define N_NODES 16384
#define IN_DIM  256
#define HEADS   2
#define OUT_CH  256
#define F_DIM   512
#define E_IN    524288

// ---------------- scratch (device globals) ----------------------------------
__device__ float    g_h   [N_NODES * F_DIM];
__device__ float    g_as  [N_NODES * HEADS];
__device__ float    g_ad  [N_NODES * HEADS];
__device__ int      g_deg [N_NODES];
__device__ int      g_off [N_NODES + 1];
__device__ int      g_csr_src[E_IN];
__device__ float    g_h2  [N_NODES * 128];
__device__ float    g_h3  [N_NODES * 64];
__device__ float    g_h4  [N_NODES * 32];
__device__ float    g_h5  [N_NODES * 4];     // x,y,z,|p|^2
__device__ int      g_is64;
__device__ __nv_bfloat16 g_ah [N_NODES * F_DIM];
__device__ __nv_bfloat16 g_al [N_NODES * F_DIM];
__device__ __nv_bfloat16 g_ah2[N_NODES * 256];
__device__ __nv_bfloat16 g_al2[N_NODES * 256];
__device__ __nv_bfloat16 g_wh [512 * 256];   // conv_W split
__device__ __nv_bfloat16 g_wl [512 * 256];
__device__ __nv_bfloat16 g_wh2[256 * 512];   // Wa split
__device__ __nv_bfloat16 g_wl2[256 * 512];
__device__ __nv_bfloat16 g_wh3[128 * 256];   // W1 split
__device__ __nv_bfloat16 g_wl3[128 * 256];

#define BUF_H   0
#define BUF_H2  3
#define BUF_H3  4
#define BUF_H4  5
__device__ __forceinline__ float* buf_ptr(int id) {
    switch (id) {
        case BUF_H:   return g_h;
        case BUF_H2:  return g_h2;
        case BUF_H3:  return g_h3;
        default:      return g_h4;
    }
}
__device__ __forceinline__ const __nv_bfloat16* w_hi(int wsel) {
    switch (wsel) { case 0: return g_wh; case 1: return g_wh2; default: return g_wh3; }
}
__device__ __forceinline__ const __nv_bfloat16* w_lo(int wsel) {
    switch (wsel) { case 0: return g_wl; case 1: return g_wl2; default: return g_wl3; }
}

// ---------------- helpers ---------------------------------------------------
__device__ __forceinline__ float lrelu(float v) { return v > 0.f ? v : 0.2f * v; }

__device__ __forceinline__ float rsqrt_approx(float x) {
    float r;
    asm("rsqrt.approx.f32 %0, %1;" : "=f"(r) : "f"(x));
    return r;
}

__device__ __forceinline__ void mma_bf16(float* c, const unsigned* a, const unsigned* b) {
    asm volatile(
        "mma.sync.aligned.m16n8k16.row.col.f32.bf16.bf16.f32 "
        "{%0,%1,%2,%3}, {%4,%5,%6,%7}, {%8,%9}, {%0,%1,%2,%3};"
        : "+f"(c[0]), "+f"(c[1]), "+f"(c[2]), "+f"(c[3])
        : "r"(a[0]), "r"(a[1]), "r"(a[2]), "r"(a[3]), "r"(b[0]), "r"(b[1]));
}

__device__ __forceinline__ void ldsm_x4(unsigned* r, unsigned saddr) {
    asm volatile("ldmatrix.sync.aligned.m8n8.x4.shared.b16 {%0,%1,%2,%3}, [%4];"
        : "=r"(r[0]), "=r"(r[1]), "=r"(r[2]), "=r"(r[3]) : "r"(saddr));
}

__device__ __forceinline__ void cp_async16s(unsigned smem_dst, const void* gsrc) {
    asm volatile("cp.async.ca.shared.global [%0], [%1], 16;" :: "r"(smem_dst), "l"(gsrc));
}
__device__ __forceinline__ void cp_commit() { asm volatile("cp.async.commit_group;"); }
template <int N>
__device__ __forceinline__ void cp_wait() {
    asm volatile("cp.async.wait_group %0;" :: "n"(N) : "memory");
}

__device__ __forceinline__ void split2(float a, float b, __nv_bfloat162& h, __nv_bfloat162& l) {
    __nv_bfloat16 ha = __float2bfloat16_rn(a);
    __nv_bfloat16 hb = __float2bfloat16_rn(b);
    h.x = ha; h.y = hb;
    l.x = __float2bfloat16_rn(a - __bfloat162float(ha));
    l.y = __float2bfloat16_rn(b - __bfloat162float(hb));
}

// ---------------- split fp32 -> bf16 hi/lo -----------------------------------
// dest: 0 = g_ah/g_al (activations), 1 = g_wh, 2 = g_wh2, 3 = g_wh3
__global__ void split_kernel(const float* __restrict__ A, int n4, int dest) {
    int i = blockIdx.x * blockDim.x + threadIdx.x;
    if (i >= n4) return;
    float4 v = ((const float4*)A)[i];
    __nv_bfloat162 h0, h1, l0, l1;
    split2(v.x, v.y, h0, l0);
    split2(v.z, v.w, h1, l1);
    __nv_bfloat162* dh;
    __nv_bfloat162* dl;
    switch (dest) {
        case 0: dh = (__nv_bfloat162*)g_ah;  dl = (__nv_bfloat162*)g_al;  break;
        case 1: dh = (__nv_bfloat162*)g_wh;  dl = (__nv_bfloat162*)g_wl;  break;
        case 2: dh = (__nv_bfloat162*)g_wh2; dl = (__nv_bfloat162*)g_wl2; break;
        default: dh = (__nv_bfloat162*)g_wh3; dl = (__nv_bfloat162*)g_wl3; break;
    }
    dh[i * 2] = h0; dh[i * 2 + 1] = h1;
    dl[i * 2] = l0; dl[i * 2 + 1] = l1;
}

// ---------------- tensor-core GEMM (256 thr, 64x32 warp tile, LDSM, 3-stage) --
#define SP 24
#define OPB  6144
#define STGB (4 * OPB)
#define NSTG 3
__global__ __launch_bounds__(256, 2)
void gemm_tc_kernel(const float* __restrict__ bias, int c_id,
                    int Nout, int K, int doRelu, int in_sel, int out_mode, int wsel) {
    extern __shared__ __align__(16) char dsm[];
    const __nv_bfloat16* Ah = in_sel ? g_ah2 : g_ah;
    const __nv_bfloat16* Al = in_sel ? g_al2 : g_al;
    const __nv_bfloat16* Wh = w_hi(wsel);
    const __nv_bfloat16* Wl = w_lo(wsel);

    const unsigned sbase = (unsigned)__cvta_generic_to_shared(dsm);
    const int tid  = threadIdx.x;
    const int m0 = blockIdx.y * 128, n0 = blockIdx.x * 128;
    const int lrow = tid >> 1, lhalf = tid & 1;
    const size_t gA = (size_t)(m0 + lrow) * K + lhalf * 8;
    const size_t gB = (size_t)(n0 + lrow) * K + lhalf * 8;
    const unsigned sofs = (lrow * SP + lhalf * 8) * 2;

    const int w = tid >> 5, lane = tid & 31;
    const int wm = (w & 1) * 64, wn = (w >> 1) * 32;
    const int gr = lane >> 2, tg = lane & 3;

    const unsigned aoff = (((lane & 15) * SP) + ((lane & 16) ? 8 : 0)) * 2;
    const unsigned boff = ((((lane & 7) + ((lane & 16) ? 8 : 0)) * SP) + ((lane & 8) ? 8 : 0)) * 2;

    float acc[4][4][4];
    #pragma unroll
    for (int mt = 0; mt < 4; mt++)
        #pragma unroll
        for (int nt = 0; nt < 4; nt++)
            #pragma unroll
            for (int r = 0; r < 4; r++) acc[mt][nt][r] = 0.f;

    const int T = K >> 4;
    #pragma unroll
    for (int s = 0; s < 2; s++) {
        if (s < T) {
            unsigned sb = sbase + s * STGB;
            int kt = s << 4;
            cp_async16s(sb + 0 * OPB + sofs, &Ah[gA + kt]);
            cp_async16s(sb + 1 * OPB + sofs, &Al[gA + kt]);
            cp_async16s(sb + 2 * OPB + sofs, &Wh[gB + kt]);
            cp_async16s(sb + 3 * OPB + sofs, &Wl[gB + kt]);
            cp_commit();
        }
    }

    for (int t = 0; t < T; t++) {
        if (t + 2 < T) {
            unsigned sb = sbase + ((t + 2) % NSTG) * STGB;
            int kt = (t + 2) << 4;
            cp_async16s(sb + 0 * OPB + sofs, &Ah[gA + kt]);
            cp_async16s(sb + 1 * OPB + sofs, &Al[gA + kt]);
            cp_async16s(sb + 2 * OPB + sofs, &Wh[gB + kt]);
            cp_async16s(sb + 3 * OPB + sofs, &Wl[gB + kt]);
            cp_commit();
            cp_wait<2>();
        } else if (t + 2 == T) {
            cp_wait<1>();
        } else {
            cp_wait<0>();
        }
        __syncthreads();

        const unsigned stg = sbase + (t % NSTG) * STGB;
        unsigned ah[4][4], al[4][4], bh[4][2], bl[4][2];
        #pragma unroll
        for (int mt = 0; mt < 4; mt++) {
            unsigned rowo = (wm + mt * 16) * SP * 2;
            ldsm_x4(ah[mt], stg + 0 * OPB + rowo + aoff);
            ldsm_x4(al[mt], stg + 1 * OPB + rowo + aoff);
        }
        #pragma unroll
        for (int np = 0; np < 2; np++) {
            unsigned rowo = (wn + np * 16) * SP * 2;
            ldsm_x4(&bh[np * 2][0], stg + 2 * OPB + rowo + boff);
            ldsm_x4(&bl[np * 2][0], stg + 3 * OPB + rowo + boff);
        }
        #pragma unroll
        for (int mt = 0; mt < 4; mt++)
            #pragma unroll
            for (int nt = 0; nt < 4; nt++) {
                mma_bf16(acc[mt][nt], ah[mt], bh[nt]);
                mma_bf16(acc[mt][nt], ah[mt], bl[nt]);
                mma_bf16(acc[mt][nt], al[mt], bh[nt]);
            }
        __syncthreads();
    }

    float* C = buf_ptr(c_id);
    #pragma unroll
    for (int mt = 0; mt < 4; mt++) {
        int row = m0 + wm + mt * 16 + gr;
        #pragma unroll
        for (int nt = 0; nt < 4; nt++) {
            int col = n0 + wn + nt * 8 + 2 * tg;
            float b0 = bias ? bias[col] : 0.f;
            float b1 = bias ? bias[col + 1] : 0.f;
            float o0 = acc[mt][nt][0] + b0, o1 = acc[mt][nt][1] + b1;
            float o2 = acc[mt][nt][2] + b0, o3 = acc[mt][nt][3] + b1;
            if (doRelu) {
                o0 = fmaxf(o0, 0.f); o1 = fmaxf(o1, 0.f);
                o2 = fmaxf(o2, 0.f); o3 = fmaxf(o3, 0.f);
            }
            if (out_mode == 0) {
                *(float2*)&C[(size_t)row * Nout + col]       = make_float2(o0, o1);
                *(float2*)&C[(size_t)(row + 8) * Nout + col] = make_float2(o2, o3);
            } else {
                __nv_bfloat162 h0, l0, h1, l1;
                split2(o0, o1, h0, l0);
                split2(o2, o3, h1, l1);
                *(__nv_bfloat162*)&g_ah2[(size_t)row * Nout + col]       = h0;
                *(__nv_bfloat162*)&g_al2[(size_t)row * Nout + col]       = l0;
                *(__nv_bfloat162*)&g_ah2[(size_t)(row + 8) * Nout + col] = h1;
                *(__nv_bfloat162*)&g_al2[(size_t)(row + 8) * Nout + col] = l1;
            }
        }
    }
}

// ---------------- edge_index dtype probe -------------------------------------
__global__ void detect_idx_kernel(const void* __restrict__ ei) {
    if (threadIdx.x == 0 && blockIdx.x == 0) {
        const long long* p = (const long long*)ei;
        int ok64 = 1;
        for (int i = 0; i < 256; i++) {
            long long v = p[i];
            if (v < 0 || v >= N_NODES) { ok64 = 0; break; }
        }
        g_is64 = ok64;
    }
}
__device__ __forceinline__ void edge_nodes(const void* __restrict__ ei, int e,
                                           int& src, int& dst) {
    if (g_is64) {
        const long long* p = (const long long*)ei;
        src = (int)p[e]; dst = (int)p[E_IN + e];
    } else {
        const int* p = (const int*)ei;
        src = p[e]; dst = p[E_IN + e];
    }
    src = min(max(src, 0), N_NODES - 1);
    dst = min(max(dst, 0), N_NODES - 1);
}

// ---------------- CSR build ---------------------------------------------------
__global__ void zero_deg_kernel() {
    int i = blockIdx.x * blockDim.x + threadIdx.x;
    if (i < N_NODES) g_deg[i] = 0;
}
__global__ void hist_kernel(const void* __restrict__ ei) {
    int e = blockIdx.x * blockDim.x + threadIdx.x;
    if (e >= E_IN) return;
    int src, dst; edge_nodes(ei, e, src, dst);
    atomicAdd(&g_deg[dst], 1);
}
__global__ __launch_bounds__(1024)
void scan_kernel() {
    __shared__ int wsum[32];
    int t = threadIdx.x;
    int base = t * 16;
    int4 d0 = *(const int4*)&g_deg[base + 0];
    int4 d1 = *(const int4*)&g_deg[base + 4];
    int4 d2 = *(const int4*)&g_deg[base + 8];
    int4 d3 = *(const int4*)&g_deg[base + 12];
    int v0 = d0.x, v1 = d0.y, v2 = d0.z, v3 = d0.w;
    int v4 = d1.x, v5 = d1.y, v6 = d1.z, v7 = d1.w;
    int v8 = d2.x, v9 = d2.y, v10 = d2.z, v11 = d2.w;
    int v12 = d3.x, v13 = d3.y, v14 = d3.z, v15 = d3.w;
    int l0=0, l1=v0, l2=l1+v1, l3=l2+v2, l4=l3+v3, l5=l4+v4, l6=l5+v5, l7=l6+v6,
        l8=l7+v7, l9=l8+v8, l10=l9+v9, l11=l10+v10, l12=l11+v11, l13=l12+v12,
        l14=l13+v13, l15=l14+v14;
    int s = l15 + v15;
    int lane = t & 31, warp = t >> 5;
    int inc = s;
    #pragma unroll
    for (int d = 1; d < 32; d <<= 1) {
        int v = __shfl_up_sync(0xffffffffu, inc, d);
        if (lane >= d) inc += v;
    }
    if (lane == 31) wsum[warp] = inc;
    __syncthreads();
    if (warp == 0) {
        int v = wsum[lane];
        #pragma unroll
        for (int d = 1; d < 32; d <<= 1) {
            int u = __shfl_up_sync(0xffffffffu, v, d);
            if (lane >= d) v += u;
        }
        wsum[lane] = v;
    }
    __syncthreads();
    int p = (warp ? wsum[warp - 1] : 0) + (inc - s);
    int4 o0 = make_int4(p+l0,  p+l1,  p+l2,  p+l3);
    int4 o1 = make_int4(p+l4,  p+l5,  p+l6,  p+l7);
    int4 o2 = make_int4(p+l8,  p+l9,  p+l10, p+l11);
    int4 o3 = make_int4(p+l12, p+l13, p+l14, p+l15);
    *(int4*)&g_off[base + 0]  = o0;  *(int4*)&g_off[base + 4]  = o1;
    *(int4*)&g_off[base + 8]  = o2;  *(int4*)&g_off[base + 12] = o3;
    *(int4*)&g_deg[base + 0]  = o0;  *(int4*)&g_deg[base + 4]  = o1;
    *(int4*)&g_deg[base + 8]  = o2;  *(int4*)&g_deg[base + 12] = o3;
    if (t == 1023) g_off[N_NODES] = E_IN;
}
__global__ void scatter_kernel(const void* __restrict__ ei) {
    int e = blockIdx.x * blockDim.x + threadIdx.x;
    if (e >= E_IN) return;
    int src, dst; edge_nodes(ei, e, src, dst);
    int pos = atomicAdd(&g_deg[dst], 1);
    g_csr_src[pos] = src;
}

// ---------------- small GEMM (Nout<128): 64x64 tile, 4x4 microtile -----------
__global__ __launch_bounds__(256)
void gemm_kernel(int a_id, const float* __restrict__ W, const float* __restrict__ bias,
                 int c_id, int Nout, int K, int doRelu) {
    const float* A = (const float*)buf_ptr(a_id);
    float* C = buf_ptr(c_id);

    __shared__ float As[16][64];
    __shared__ float Ws[16][64];
    const int tid = threadIdx.x;
    const int tx = tid & 15, ty = tid >> 4;
    const int m0 = blockIdx.y * 64;
    const int n0 = blockIdx.x * 64;
    const int lr = tid >> 2;
    const int lc = (tid & 3) * 4;

    float acc[4][4];
    #pragma unroll
    for (int i = 0; i < 4; i++)
        #pragma unroll
        for (int j = 0; j < 4; j++) acc[i][j] = 0.f;

    for (int kt = 0; kt < K; kt += 16) {
        float4 av = *(const float4*)&A[(size_t)(m0 + lr) * K + kt + lc];
        As[lc + 0][lr] = av.x; As[lc + 1][lr] = av.y;
        As[lc + 2][lr] = av.z; As[lc + 3][lr] = av.w;
        float4 wv = make_float4(0.f, 0.f, 0.f, 0.f);
        if (n0 + lr < Nout)
            wv = *(const float4*)&W[(size_t)(n0 + lr) * K + kt + lc];
        Ws[lc + 0][lr] = wv.x; Ws[lc + 1][lr] = wv.y;
        Ws[lc + 2][lr] = wv.z; Ws[lc + 3][lr] = wv.w;
        __syncthreads();
        #pragma unroll
        for (int k = 0; k < 16; k++) {
            float4 a = *(const float4*)&As[k][ty * 4];
            float4 b = *(const float4*)&Ws[k][tx * 4];
            acc[0][0] = fmaf(a.x, b.x, acc[0][0]); acc[0][1] = fmaf(a.x, b.y, acc[0][1]);
            acc[0][2] = fmaf(a.x, b.z, acc[0][2]); acc[0][3] = fmaf(a.x, b.w, acc[0][3]);
            acc[1][0] = fmaf(a.y, b.x, acc[1][0]); acc[1][1] = fmaf(a.y, b.y, acc[1][1]);
            acc[1][2] = fmaf(a.y, b.z, acc[1][2]); acc[1][3] = fmaf(a.y, b.w, acc[1][3]);
            acc[2][0] = fmaf(a.z, b.x, acc[2][0]); acc[2][1] = fmaf(a.z, b.y, acc[2][1]);
            acc[2][2] = fmaf(a.z, b.z, acc[2][2]); acc[2][3] = fmaf(a.z, b.w, acc[2][3]);
            acc[3][0] = fmaf(a.w, b.x, acc[3][0]); acc[3][1] = fmaf(a.w, b.y, acc[3][1]);
            acc[3][2] = fmaf(a.w, b.z, acc[3][2]); acc[3][3] = fmaf(a.w, b.w, acc[3][3]);
        }
        __syncthreads();
    }

    const int col = n0 + tx * 4;
    if (col < Nout) {
        float bx = bias[col], by = bias[col + 1], bz = bias[col + 2], bw = bias[col + 3];
        #pragma unroll
        for (int i = 0; i < 4; i++) {
            int row = m0 + ty * 4 + i;
            float4 v = make_float4(acc[i][0] + bx, acc[i][1] + by,
                                   acc[i][2] + bz, acc[i][3] + bw);
            if (doRelu) {
                v.x = fmaxf(v.x, 0.f); v.y = fmaxf(v.y, 0.f);
                v.z = fmaxf(v.z, 0.f); v.w = fmaxf(v.w, 0.f);
            }
            *(float4*)&C[(size_t)row * Nout + col] = v;
        }
    }
}

// ---------------- attention scores: warp per (node, head) --------------------
__global__ void attn_scores_kernel(const float* __restrict__ att_src,
                                   const float* __restrict__ att_dst) {
    int gw = (blockIdx.x * blockDim.x + threadIdx.x) >> 5;
    int lane = threadIdx.x & 31;
    if (gw >= N_NODES * HEADS) return;
    int node = gw >> 1, head = gw & 1;
    const float* hp = g_h + (size_t)node * F_DIM + head * OUT_CH + lane * 8;
    const float* sp = att_src + head * OUT_CH + lane * 8;
    const float* dp = att_dst + head * OUT_CH + lane * 8;
    float4 h0 = *(const float4*)hp,  h1 = *(const float4*)(hp + 4);
    float4 s0 = *(const float4*)sp,  s1 = *(const float4*)(sp + 4);
    float4 d0 = *(const float4*)dp,  d1 = *(const float4*)(dp + 4);
    float s = h0.x * s0.x + h0.y * s0.y + h0.z * s0.z + h0.w * s0.w
            + h1.x * s1.x + h1.y * s1.y + h1.z * s1.z + h1.w * s1.w;
    float d = h0.x * d0.x + h0.y * d0.y + h0.z * d0.z + h0.w * d0.w
            + h1.x * d1.x + h1.y * d1.y + h1.z * d1.z + h1.w * d1.w;
    #pragma unroll
    for (int o = 16; o; o >>= 1) {
        s += __shfl_xor_sync(0xffffffffu, s, o);
        d += __shfl_xor_sync(0xffffffffu, d, o);
    }
    if (lane == 0) { g_as[gw] = s; g_ad[gw] = d; }
}

// ---------------- fused GAT: softmax + aggregate + bias + relu + bf16 split --
__global__ __launch_bounds__(128)
void gat_agg_kernel(const float* __restrict__ conv_b) {
    const int dst = blockIdx.x;
    const int t = threadIdx.x;
    __shared__ float red[128];
    __shared__ float sh_a0[128], sh_a1[128];
    __shared__ int   sh_src[128];
    __shared__ float sm0, sm1, ss0, ss1;

    const int off = g_off[dst];
    const int deg = g_off[dst + 1] - off;
    const float ad0 = g_ad[dst * 2], ad1 = g_ad[dst * 2 + 1];
    const float self0 = lrelu(g_as[dst * 2] + ad0);
    const float self1 = lrelu(g_as[dst * 2 + 1] + ad1);

    float m0 = self0, m1 = self1;
    for (int j = t; j < deg; j += 128) {
        int s = g_csr_src[off + j];
        m0 = fmaxf(m0, lrelu(g_as[s * 2] + ad0));
        m1 = fmaxf(m1, lrelu(g_as[s * 2 + 1] + ad1));
    }
    red[t] = m0; __syncthreads();
    for (int d = 64; d; d >>= 1) { if (t < d) red[t] = fmaxf(red[t], red[t + d]); __syncthreads(); }
    if (t == 0) sm0 = red[0];
    __syncthreads();
    red[t] = m1; __syncthreads();
    for (int d = 64; d; d >>= 1) { if (t < d) red[t] = fmaxf(red[t], red[t + d]); __syncthreads(); }
    if (t == 0) sm1 = red[0];
    __syncthreads();
    m0 = sm0; m1 = sm1;

    float s0 = (t == 0) ? expf(self0 - m0) : 0.f;
    float s1 = (t == 0) ? expf(self1 - m1) : 0.f;
    for (int j = t; j < deg; j += 128) {
        int s = g_csr_src[off + j];
        s0 += expf(lrelu(g_as[s * 2] + ad0) - m0);
        s1 += expf(lrelu(g_as[s * 2 + 1] + ad1) - m1);
    }
    red[t] = s0; __syncthreads();
    for (int d = 64; d; d >>= 1) { if (t < d) red[t] += red[t + d]; __syncthreads(); }
    if (t == 0) ss0 = red[0];
    __syncthreads();
    red[t] = s1; __syncthreads();
    for (int d = 64; d; d >>= 1) { if (t < d) red[t] += red[t + d]; __syncthreads(); }
    if (t == 0) ss1 = red[0];
    __syncthreads();
    const float rs0 = 1.f / ss0, rs1 = 1.f / ss1;

    const int head = t >> 6;
    const float mself  = head ? self1 : self0;
    const float mmax   = head ? sm1 : sm0;
    const float rss    = head ? rs1 : rs0;
    const float a_self = expf(mself - mmax) * rss;

    float4 v = *(const float4*)&g_h[(size_t)dst * F_DIM + t * 4];
    float4 acc = make_float4(a_self * v.x, a_self * v.y, a_self * v.z, a_self * v.w);

    for (int c = 0; c < deg; c += 128) {
        int j = c + t;
        if (j < deg) {
            int s = g_csr_src[off + j];
            sh_src[t] = s;
            sh_a0[t] = expf(lrelu(g_as[s * 2] + ad0) - sm0) * rs0;
            sh_a1[t] = expf(lrelu(g_as[s * 2 + 1] + ad1) - sm1) * rs1;
        }
        __syncthreads();
        int cnt = min(128, deg - c);
        for (int j2 = 0; j2 < cnt; j2++) {
            const float4 hv = *(const float4*)&g_h[(size_t)sh_src[j2] * F_DIM + t * 4];
            float a = head ? sh_a1[j2] : sh_a0[j2];
            acc.x = fmaf(a, hv.x, acc.x);
            acc.y = fmaf(a, hv.y, acc.y);
            acc.z = fmaf(a, hv.z, acc.z);
            acc.w = fmaf(a, hv.w, acc.w);
        }
        __syncthreads();
    }

    float4 b = *(const float4*)&conv_b[t * 4];
    acc.x = fmaxf(acc.x + b.x, 0.f);
    acc.y = fmaxf(acc.y + b.y, 0.f);
    acc.z = fmaxf(acc.z + b.z, 0.f);
    acc.w = fmaxf(acc.w + b.w, 0.f);
    __nv_bfloat162 h0, l0, h1, l1;
    split2(acc.x, acc.y, h0, l0);
    split2(acc.z, acc.w, h1, l1);
    size_t idx = (size_t)dst * F_DIM + t * 4;
    *(__nv_bfloat162*)&g_ah[idx]     = h0;
    *(__nv_bfloat162*)&g_ah[idx + 2] = h1;
    *(__nv_bfloat162*)&g_al[idx]     = l0;
    *(__nv_bfloat162*)&g_al[idx + 2] = l1;
}

// ---------------- last MLP layer: 32 -> 3, also store |p|^2 -------------------
__global__ __launch_bounds__(256)
void final_layer_kernel(const float* __restrict__ W4, const float* __restrict__ b4) {
    __shared__ float w[3][32];
    __shared__ float bb[3];
    int tid = threadIdx.x;
    if (tid < 96) w[tid / 32][tid & 31] = W4[tid];
    if (tid < 3)  bb[tid] = b4[tid];
    __syncthreads();
    int n = blockIdx.x * blockDim.x + tid;
    if (n >= N_NODES) return;
    const float4* hp = (const float4*)(g_h4 + (size_t)n * 32);
    float a0 = bb[0], a1 = bb[1], a2 = bb[2];
    #pragma unroll
    for (int q = 0; q < 8; q++) {
        float4 v = hp[q];
        a0 = fmaf(v.x, w[0][q*4+0], a0); a0 = fmaf(v.y, w[0][q*4+1], a0);
        a0 = fmaf(v.z, w[0][q*4+2], a0); a0 = fmaf(v.w, w[0][q*4+3], a0);
        a1 = fmaf(v.x, w[1][q*4+0], a1); a1 = fmaf(v.y, w[1][q*4+1], a1);
        a1 = fmaf(v.z, w[1][q*4+2], a1); a1 = fmaf(v.w, w[1][q*4+3], a1);
        a2 = fmaf(v.x, w[2][q*4+0], a2); a2 = fmaf(v.y, w[2][q*4+1], a2);
        a2 = fmaf(v.z, w[2][q*4+2], a2); a2 = fmaf(v.w, w[2][q*4+3], a2);
    }
    float sq = fmaf(a0, a0, fmaf(a1, a1, a2 * a2));
    ((float4*)g_h5)[n] = make_float4(a0, a1, a2, sq);
}

// ---------------- pairwise distances: d2 = sp+sq-2*dot, MUFU rsqrt ------------
__global__ __launch_bounds__(256)
void cdist_kernel(float* __restrict__ out) {
    __shared__ float4 rp[128];
    __shared__ float4 cp[128];
    int tid = threadIdx.x;
    int rb = blockIdx.y * 128, cb = blockIdx.x * 128;
    if (tid < 128) rp[tid] = ((const float4*)g_h5)[rb + tid];
    else           cp[tid - 128] = ((const float4*)g_h5)[cb + tid - 128];
    __syncthreads();
    int tx = tid & 31, ty = tid >> 5;
    float4 q0 = cp[tx * 4 + 0], q1 = cp[tx * 4 + 1],
           q2 = cp[tx * 4 + 2], q3 = cp[tx * 4 + 3];
    #pragma unroll
    for (int j = 0; j < 16; j++) {
        int r = j * 8 + ty;
        float4 p = rp[r];
        float4 o;
        float t, d2;
        t = p.x * q0.x; t = fmaf(p.y, q0.y, t); t = fmaf(p.z, q0.z, t);
        d2 = fmaf(-2.f, t, p.w + q0.w); d2 = fmaxf(d2, 0.f);
        o.x = d2 * rsqrt_approx(fmaxf(d2, 1e-35f));
        t = p.x * q1.x; t = fmaf(p.y, q1.y, t); t = fmaf(p.z, q1.z, t);
        d2 = fmaf(-2.f, t, p.w + q1.w); d2 = fmaxf(d2, 0.f);
        o.y = d2 * rsqrt_approx(fmaxf(d2, 1e-35f));
        t = p.x * q2.x; t = fmaf(p.y, q2.y, t); t = fmaf(p.z, q2.z, t);
        d2 = fmaf(-2.f, t, p.w + q2.w); d2 = fmaxf(d2, 0.f);
        o.z = d2 * rsqrt_approx(fmaxf(d2, 1e-35f));
        t = p.x * q3.x; t = fmaf(p.y, q3.y, t); t = fmaf(p.z, q3.z, t);
        d2 = fmaf(-2.f, t, p.w + q3.w); d2 = fmaxf(d2, 0.f);
        o.w = d2 * rsqrt_approx(fmaxf(d2, 1e-35f));
        __stcs((float4*)&out[(size_t)(rb + r) * N_NODES + cb + tx * 4], o);
    }
}

// ---------------- launch -------------------------------------------------------
extern "C" void kernel_launch(void* const* d_in, const int* in_sizes, int n_in,
                              void* d_out, int out_size) {
    const float* x       = (const float*)d_in[0];
    const void*  ei      = (const void*)d_in[1];
    const float* conv_W  = (const float*)d_in[2];
    const float* att_src = (const float*)d_in[3];
    const float* att_dst = (const float*)d_in[4];
    const float* conv_b  = (const float*)d_in[5];
    const float* Wa = (const float*)d_in[6];  const float* ba = (const float*)d_in[7];
    const float* W1 = (const float*)d_in[8];  const float* b1 = (const float*)d_in[9];
    const float* W2 = (const float*)d_in[10]; const float* b2 = (const float*)d_in[11];
    const float* W3 = (const float*)d_in[12]; const float* b3 = (const float*)d_in[13];
    const float* W4 = (const float*)d_in[14]; const float* b4 = (const float*)d_in[15];
    float*       out = (float*)d_out;

    const int TCSMEM = NSTG * STGB;
    static bool init_done = false;
    static cudaStream_t s2;
    static cudaEvent_t evFork, evJoin;
    if (!init_done) {
        cudaFuncSetAttribute(gemm_tc_kernel,
                             cudaFuncAttributeMaxDynamicSharedMemorySize, TCSMEM);
        cudaStreamCreateWithFlags(&s2, cudaStreamNonBlocking);
        cudaEventCreateWithFlags(&evFork, cudaEventDisableTiming);
        cudaEventCreateWithFlags(&evJoin, cudaEventDisableTiming);
        init_done = true;
    }

    // main stream: dtype probe first (needed by side stream's hist/scatter)
    detect_idx_kernel<<<1, 32>>>(ei);
    cudaEventRecord(evFork, 0);
    cudaStreamWaitEvent(s2, evFork, 0);

    // side stream: all weight splits + CSR build (independent of conv chain)
    split_kernel<<<(F_DIM * IN_DIM / 4 + 255) / 256, 256, 0, s2>>>(conv_W, F_DIM * IN_DIM / 4, 1);
    split_kernel<<<(256 * 512 / 4 + 255) / 256, 256, 0, s2>>>(Wa, 256 * 512 / 4, 2);
    split_kernel<<<(128 * 256 / 4 + 255) / 256, 256, 0, s2>>>(W1, 128 * 256 / 4, 3);
    zero_deg_kernel<<<(N_NODES + 255) / 256, 256, 0, s2>>>();
    hist_kernel<<<(E_IN + 255) / 256, 256, 0, s2>>>(ei);
    scan_kernel<<<1, 1024, 0, s2>>>();
    scatter_kernel<<<(E_IN + 255) / 256, 256, 0, s2>>>(ei);
    cudaEventRecord(evJoin, s2);

    // main stream: activation split
    split_kernel<<<(N_NODES * IN_DIM / 4 + 255) / 256, 256>>>(x, N_NODES * IN_DIM / 4, 0);

    // conv GEMM needs conv_W split (on s2): join the weight-split portion too.
    // (evJoin covers the whole s2 chain; wait once here — CSR also done by agg time.)
    cudaStreamWaitEvent(0, evJoin, 0);

    // conv GEMM: h = x @ conv_W^T
    gemm_tc_kernel<<<dim3(F_DIM / 128, N_NODES / 128), 256, TCSMEM>>>(
        nullptr, BUF_H, F_DIM, IN_DIM, 0, 0, 0, 0);

    attn_scores_kernel<<<(N_NODES * HEADS * 32 + 255) / 256, 256>>>(att_src, att_dst);
    gat_agg_kernel<<<N_NODES, 128>>>(conv_b);

    // Wa: [N,512] -> [N,256]
    gemm_tc_kernel<<<dim3(256 / 128, N_NODES / 128), 256, TCSMEM>>>(
        ba, BUF_H, 256, 512, 1, 0, 1, 1);

    // W1: [N,256] -> [N,128]
    gemm_tc_kernel<<<dim3(128 / 128, N_NODES / 128), 256, TCSMEM>>>(
        b1, BUF_H2, 128, 256, 1, 1, 0, 2);

    // small layers fp32 SIMT
    gemm_kernel<<<dim3(1, N_NODES / 64), 256>>>(BUF_H2, W2, b2, BUF_H3, 64, 128, 1);
    gemm_kernel<<<dim3(1, N_NODES / 64), 256>>>(BUF_H3, W3, b3, BUF_H4, 32, 64, 1);
    final_layer_kernel<<<N_NODES / 256, 256>>>(W4, b4);

    cdist_kernel<<<dim3(N_NODES / 128, N_NODES / 128), 256>>>(out);
}

// round 16
// speedup vs baseline: 1.1305x; 1.0048x over previous
#include <cuda_runtime.h>
#include <cuda_bf16.h>
#include <math.h>

#define N_NODES 16384
#define IN_DIM  256
#define HEADS   2
#define OUT_CH  256
#define F_DIM   512
#define E_IN    524288

// ---------------- scratch (device globals) ----------------------------------
__device__ float    g_h   [N_NODES * F_DIM];
__device__ float    g_as  [N_NODES * HEADS];
__device__ float    g_ad  [N_NODES * HEADS];
__device__ int      g_deg [N_NODES];
__device__ int      g_off [N_NODES + 1];
__device__ int      g_csr_src[E_IN];
__device__ float    g_h2  [N_NODES * 128];
__device__ float    g_h3  [N_NODES * 64];
__device__ float    g_h4  [N_NODES * 32];
__device__ float    g_h5  [N_NODES * 4];     // x,y,z,|p|^2
__device__ int      g_is64;
__device__ __nv_bfloat16 g_ah [N_NODES * F_DIM];
__device__ __nv_bfloat16 g_al [N_NODES * F_DIM];
__device__ __nv_bfloat16 g_ah2[N_NODES * 256];
__device__ __nv_bfloat16 g_al2[N_NODES * 256];
__device__ __nv_bfloat16 g_wh [512 * 256];
__device__ __nv_bfloat16 g_wl [512 * 256];
__device__ __nv_bfloat16 g_wh2[256 * 512];
__device__ __nv_bfloat16 g_wl2[256 * 512];
__device__ __nv_bfloat16 g_wh3[128 * 256];
__device__ __nv_bfloat16 g_wl3[128 * 256];

#define BUF_H   0
#define BUF_H2  3
#define BUF_H3  4
#define BUF_H4  5
__device__ __forceinline__ float* buf_ptr(int id) {
    switch (id) {
        case BUF_H:   return g_h;
        case BUF_H2:  return g_h2;
        case BUF_H3:  return g_h3;
        default:      return g_h4;
    }
}
__device__ __forceinline__ const __nv_bfloat16* w_hi(int wsel) {
    switch (wsel) { case 0: return g_wh; case 1: return g_wh2; default: return g_wh3; }
}
__device__ __forceinline__ const __nv_bfloat16* w_lo(int wsel) {
    switch (wsel) { case 0: return g_wl; case 1: return g_wl2; default: return g_wl3; }
}

// ---------------- helpers ---------------------------------------------------
__device__ __forceinline__ float lrelu(float v) { return v > 0.f ? v : 0.2f * v; }

__device__ __forceinline__ float rsqrt_approx(float x) {
    float r;
    asm("rsqrt.approx.f32 %0, %1;" : "=f"(r) : "f"(x));
    return r;
}

__device__ __forceinline__ void mma_bf16(float* c, const unsigned* a, const unsigned* b) {
    asm volatile(
        "mma.sync.aligned.m16n8k16.row.col.f32.bf16.bf16.f32 "
        "{%0,%1,%2,%3}, {%4,%5,%6,%7}, {%8,%9}, {%0,%1,%2,%3};"
        : "+f"(c[0]), "+f"(c[1]), "+f"(c[2]), "+f"(c[3])
        : "r"(a[0]), "r"(a[1]), "r"(a[2]), "r"(a[3]), "r"(b[0]), "r"(b[1]));
}

__device__ __forceinline__ void ldsm_x4(unsigned* r, unsigned saddr) {
    asm volatile("ldmatrix.sync.aligned.m8n8.x4.shared.b16 {%0,%1,%2,%3}, [%4];"
        : "=r"(r[0]), "=r"(r[1]), "=r"(r[2]), "=r"(r[3]) : "r"(saddr));
}

__device__ __forceinline__ void cp_async16s(unsigned smem_dst, const void* gsrc) {
    asm volatile("cp.async.ca.shared.global [%0], [%1], 16;" :: "r"(smem_dst), "l"(gsrc));
}
__device__ __forceinline__ void cp_commit() { asm volatile("cp.async.commit_group;"); }
template <int N>
__device__ __forceinline__ void cp_wait() {
    asm volatile("cp.async.wait_group %0;" :: "n"(N) : "memory");
}

__device__ __forceinline__ void split2(float a, float b, __nv_bfloat162& h, __nv_bfloat162& l) {
    __nv_bfloat16 ha = __float2bfloat16_rn(a);
    __nv_bfloat16 hb = __float2bfloat16_rn(b);
    h.x = ha; h.y = hb;
    l.x = __float2bfloat16_rn(a - __bfloat162float(ha));
    l.y = __float2bfloat16_rn(b - __bfloat162float(hb));
}

// ---------------- split fp32 -> bf16 hi/lo -----------------------------------
__global__ void split_kernel(const float* __restrict__ A, int n4, int dest) {
    int i = blockIdx.x * blockDim.x + threadIdx.x;
    if (i >= n4) return;
    float4 v = ((const float4*)A)[i];
    __nv_bfloat162 h0, h1, l0, l1;
    split2(v.x, v.y, h0, l0);
    split2(v.z, v.w, h1, l1);
    __nv_bfloat162* dh;
    __nv_bfloat162* dl;
    switch (dest) {
        case 0: dh = (__nv_bfloat162*)g_ah;  dl = (__nv_bfloat162*)g_al;  break;
        case 1: dh = (__nv_bfloat162*)g_wh;  dl = (__nv_bfloat162*)g_wl;  break;
        case 2: dh = (__nv_bfloat162*)g_wh2; dl = (__nv_bfloat162*)g_wl2; break;
        default: dh = (__nv_bfloat162*)g_wh3; dl = (__nv_bfloat162*)g_wl3; break;
    }
    dh[i * 2] = h0; dh[i * 2 + 1] = h1;
    dl[i * 2] = l0; dl[i * 2 + 1] = l1;
}

// ---------------- tensor-core GEMM (256 thr, 64x32 warp tile, LDSM, 3-stage) --
#define SP 24
#define OPB  6144
#define STGB (4 * OPB)
#define NSTG 3
__global__ __launch_bounds__(256, 2)
void gemm_tc_kernel(const float* __restrict__ bias, int c_id,
                    int Nout, int K, int doRelu, int in_sel, int out_mode, int wsel) {
    extern __shared__ __align__(16) char dsm[];
    const __nv_bfloat16* Ah = in_sel ? g_ah2 : g_ah;
    const __nv_bfloat16* Al = in_sel ? g_al2 : g_al;
    const __nv_bfloat16* Wh = w_hi(wsel);
    const __nv_bfloat16* Wl = w_lo(wsel);

    const unsigned sbase = (unsigned)__cvta_generic_to_shared(dsm);
    const int tid  = threadIdx.x;
    const int m0 = blockIdx.y * 128, n0 = blockIdx.x * 128;
    const int lrow = tid >> 1, lhalf = tid & 1;
    const size_t gA = (size_t)(m0 + lrow) * K + lhalf * 8;
    const size_t gB = (size_t)(n0 + lrow) * K + lhalf * 8;
    const unsigned sofs = (lrow * SP + lhalf * 8) * 2;

    const int w = tid >> 5, lane = tid & 31;
    const int wm = (w & 1) * 64, wn = (w >> 1) * 32;
    const int gr = lane >> 2, tg = lane & 3;

    const unsigned aoff = (((lane & 15) * SP) + ((lane & 16) ? 8 : 0)) * 2;
    const unsigned boff = ((((lane & 7) + ((lane & 16) ? 8 : 0)) * SP) + ((lane & 8) ? 8 : 0)) * 2;

    float acc[4][4][4];
    #pragma unroll
    for (int mt = 0; mt < 4; mt++)
        #pragma unroll
        for (int nt = 0; nt < 4; nt++)
            #pragma unroll
            for (int r = 0; r < 4; r++) acc[mt][nt][r] = 0.f;

    const int T = K >> 4;
    #pragma unroll
    for (int s = 0; s < 2; s++) {
        if (s < T) {
            unsigned sb = sbase + s * STGB;
            int kt = s << 4;
            cp_async16s(sb + 0 * OPB + sofs, &Ah[gA + kt]);
            cp_async16s(sb + 1 * OPB + sofs, &Al[gA + kt]);
            cp_async16s(sb + 2 * OPB + sofs, &Wh[gB + kt]);
            cp_async16s(sb + 3 * OPB + sofs, &Wl[gB + kt]);
            cp_commit();
        }
    }

    for (int t = 0; t < T; t++) {
        if (t + 2 < T) {
            unsigned sb = sbase + ((t + 2) % NSTG) * STGB;
            int kt = (t + 2) << 4;
            cp_async16s(sb + 0 * OPB + sofs, &Ah[gA + kt]);
            cp_async16s(sb + 1 * OPB + sofs, &Al[gA + kt]);
            cp_async16s(sb + 2 * OPB + sofs, &Wh[gB + kt]);
            cp_async16s(sb + 3 * OPB + sofs, &Wl[gB + kt]);
            cp_commit();
            cp_wait<2>();
        } else if (t + 2 == T) {
            cp_wait<1>();
        } else {
            cp_wait<0>();
        }
        __syncthreads();

        const unsigned stg = sbase + (t % NSTG) * STGB;
        unsigned ah[4][4], al[4][4], bh[4][2], bl[4][2];
        #pragma unroll
        for (int mt = 0; mt < 4; mt++) {
            unsigned rowo = (wm + mt * 16) * SP * 2;
            ldsm_x4(ah[mt], stg + 0 * OPB + rowo + aoff);
            ldsm_x4(al[mt], stg + 1 * OPB + rowo + aoff);
        }
        #pragma unroll
        for (int np = 0; np < 2; np++) {
            unsigned rowo = (wn + np * 16) * SP * 2;
            ldsm_x4(&bh[np * 2][0], stg + 2 * OPB + rowo + boff);
            ldsm_x4(&bl[np * 2][0], stg + 3 * OPB + rowo + boff);
        }
        // product-major order: 16 independent accumulators between reuses
        #pragma unroll
        for (int mt = 0; mt < 4; mt++)
            #pragma unroll
            for (int nt = 0; nt < 4; nt++)
                mma_bf16(acc[mt][nt], ah[mt], bh[nt]);
        #pragma unroll
        for (int mt = 0; mt < 4; mt++)
            #pragma unroll
            for (int nt = 0; nt < 4; nt++)
                mma_bf16(acc[mt][nt], ah[mt], bl[nt]);
        #pragma unroll
        for (int mt = 0; mt < 4; mt++)
            #pragma unroll
            for (int nt = 0; nt < 4; nt++)
                mma_bf16(acc[mt][nt], al[mt], bh[nt]);
        __syncthreads();
    }

    float* C = buf_ptr(c_id);
    #pragma unroll
    for (int mt = 0; mt < 4; mt++) {
        int row = m0 + wm + mt * 16 + gr;
        #pragma unroll
        for (int nt = 0; nt < 4; nt++) {
            int col = n0 + wn + nt * 8 + 2 * tg;
            float b0 = bias ? bias[col] : 0.f;
            float b1 = bias ? bias[col + 1] : 0.f;
            float o0 = acc[mt][nt][0] + b0, o1 = acc[mt][nt][1] + b1;
            float o2 = acc[mt][nt][2] + b0, o3 = acc[mt][nt][3] + b1;
            if (doRelu) {
                o0 = fmaxf(o0, 0.f); o1 = fmaxf(o1, 0.f);
                o2 = fmaxf(o2, 0.f); o3 = fmaxf(o3, 0.f);
            }
            if (out_mode == 0) {
                *(float2*)&C[(size_t)row * Nout + col]       = make_float2(o0, o1);
                *(float2*)&C[(size_t)(row + 8) * Nout + col] = make_float2(o2, o3);
            } else {
                __nv_bfloat162 h0, l0, h1, l1;
                split2(o0, o1, h0, l0);
                split2(o2, o3, h1, l1);
                *(__nv_bfloat162*)&g_ah2[(size_t)row * Nout + col]       = h0;
                *(__nv_bfloat162*)&g_al2[(size_t)row * Nout + col]       = l0;
                *(__nv_bfloat162*)&g_ah2[(size_t)(row + 8) * Nout + col] = h1;
                *(__nv_bfloat162*)&g_al2[(size_t)(row + 8) * Nout + col] = l1;
            }
        }
    }
}

// ---------------- edge_index dtype probe -------------------------------------
__global__ void detect_idx_kernel(const void* __restrict__ ei) {
    if (threadIdx.x == 0 && blockIdx.x == 0) {
        const long long* p = (const long long*)ei;
        int ok64 = 1;
        for (int i = 0; i < 256; i++) {
            long long v = p[i];
            if (v < 0 || v >= N_NODES) { ok64 = 0; break; }
        }
        g_is64 = ok64;
    }
}
__device__ __forceinline__ void edge_nodes(const void* __restrict__ ei, int e,
                                           int& src, int& dst) {
    if (g_is64) {
        const long long* p = (const long long*)ei;
        src = (int)p[e]; dst = (int)p[E_IN + e];
    } else {
        const int* p = (const int*)ei;
        src = p[e]; dst = p[E_IN + e];
    }
    src = min(max(src, 0), N_NODES - 1);
    dst = min(max(dst, 0), N_NODES - 1);
}

// ---------------- CSR build ---------------------------------------------------
__global__ void zero_deg_kernel() {
    int i = blockIdx.x * blockDim.x + threadIdx.x;
    if (i < N_NODES) g_deg[i] = 0;
}
__global__ void hist_kernel(const void* __restrict__ ei) {
    int e = blockIdx.x * blockDim.x + threadIdx.x;
    if (e >= E_IN) return;
    int src, dst; edge_nodes(ei, e, src, dst);
    atomicAdd(&g_deg[dst], 1);
}
__global__ __launch_bounds__(1024)
void scan_kernel() {
    __shared__ int wsum[32];
    int t = threadIdx.x;
    int base = t * 16;
    int4 d0 = *(const int4*)&g_deg[base + 0];
    int4 d1 = *(const int4*)&g_deg[base + 4];
    int4 d2 = *(const int4*)&g_deg[base + 8];
    int4 d3 = *(const int4*)&g_deg[base + 12];
    int v0 = d0.x, v1 = d0.y, v2 = d0.z, v3 = d0.w;
    int v4 = d1.x, v5 = d1.y, v6 = d1.z, v7 = d1.w;
    int v8 = d2.x, v9 = d2.y, v10 = d2.z, v11 = d2.w;
    int v12 = d3.x, v13 = d3.y, v14 = d3.z, v15 = d3.w;
    int l0=0, l1=v0, l2=l1+v1, l3=l2+v2, l4=l3+v3, l5=l4+v4, l6=l5+v5, l7=l6+v6,
        l8=l7+v7, l9=l8+v8, l10=l9+v9, l11=l10+v10, l12=l11+v11, l13=l12+v12,
        l14=l13+v13, l15=l14+v14;
    int s = l15 + v15;
    int lane = t & 31, warp = t >> 5;
    int inc = s;
    #pragma unroll
    for (int d = 1; d < 32; d <<= 1) {
        int v = __shfl_up_sync(0xffffffffu, inc, d);
        if (lane >= d) inc += v;
    }
    if (lane == 31) wsum[warp] = inc;
    __syncthreads();
    if (warp == 0) {
        int v = wsum[lane];
        #pragma unroll
        for (int d = 1; d < 32; d <<= 1) {
            int u = __shfl_up_sync(0xffffffffu, v, d);
            if (lane >= d) v += u;
        }
        wsum[lane] = v;
    }
    __syncthreads();
    int p = (warp ? wsum[warp - 1] : 0) + (inc - s);
    int4 o0 = make_int4(p+l0,  p+l1,  p+l2,  p+l3);
    int4 o1 = make_int4(p+l4,  p+l5,  p+l6,  p+l7);
    int4 o2 = make_int4(p+l8,  p+l9,  p+l10, p+l11);
    int4 o3 = make_int4(p+l12, p+l13, p+l14, p+l15);
    *(int4*)&g_off[base + 0]  = o0;  *(int4*)&g_off[base + 4]  = o1;
    *(int4*)&g_off[base + 8]  = o2;  *(int4*)&g_off[base + 12] = o3;
    *(int4*)&g_deg[base + 0]  = o0;  *(int4*)&g_deg[base + 4]  = o1;
    *(int4*)&g_deg[base + 8]  = o2;  *(int4*)&g_deg[base + 12] = o3;
    if (t == 1023) g_off[N_NODES] = E_IN;
}
__global__ void scatter_kernel(const void* __restrict__ ei) {
    int e = blockIdx.x * blockDim.x + threadIdx.x;
    if (e >= E_IN) return;
    int src, dst; edge_nodes(ei, e, src, dst);
    int pos = atomicAdd(&g_deg[dst], 1);
    g_csr_src[pos] = src;
}

// ---------------- small GEMM (Nout<128): 64x64 tile, 4x4 microtile -----------
__global__ __launch_bounds__(256)
void gemm_kernel(int a_id, const float* __restrict__ W, const float* __restrict__ bias,
                 int c_id, int Nout, int K, int doRelu) {
    const float* A = (const float*)buf_ptr(a_id);
    float* C = buf_ptr(c_id);

    __shared__ float As[16][64];
    __shared__ float Ws[16][64];
    const int tid = threadIdx.x;
    const int tx = tid & 15, ty = tid >> 4;
    const int m0 = blockIdx.y * 64;
    const int n0 = blockIdx.x * 64;
    const int lr = tid >> 2;
    const int lc = (tid & 3) * 4;

    float acc[4][4];
    #pragma unroll
    for (int i = 0; i < 4; i++)
        #pragma unroll
        for (int j = 0; j < 4; j++) acc[i][j] = 0.f;

    for (int kt = 0; kt < K; kt += 16) {
        float4 av = *(const float4*)&A[(size_t)(m0 + lr) * K + kt + lc];
        As[lc + 0][lr] = av.x; As[lc + 1][lr] = av.y;
        As[lc + 2][lr] = av.z; As[lc + 3][lr] = av.w;
        float4 wv = make_float4(0.f, 0.f, 0.f, 0.f);
        if (n0 + lr < Nout)
            wv = *(const float4*)&W[(size_t)(n0 + lr) * K + kt + lc];
        Ws[lc + 0][lr] = wv.x; Ws[lc + 1][lr] = wv.y;
        Ws[lc + 2][lr] = wv.z; Ws[lc + 3][lr] = wv.w;
        __syncthreads();
        #pragma unroll
        for (int k = 0; k < 16; k++) {
            float4 a = *(const float4*)&As[k][ty * 4];
            float4 b = *(const float4*)&Ws[k][tx * 4];
            acc[0][0] = fmaf(a.x, b.x, acc[0][0]); acc[0][1] = fmaf(a.x, b.y, acc[0][1]);
            acc[0][2] = fmaf(a.x, b.z, acc[0][2]); acc[0][3] = fmaf(a.x, b.w, acc[0][3]);
            acc[1][0] = fmaf(a.y, b.x, acc[1][0]); acc[1][1] = fmaf(a.y, b.y, acc[1][1]);
            acc[1][2] = fmaf(a.y, b.z, acc[1][2]); acc[1][3] = fmaf(a.y, b.w, acc[1][3]);
            acc[2][0] = fmaf(a.z, b.x, acc[2][0]); acc[2][1] = fmaf(a.z, b.y, acc[2][1]);
            acc[2][2] = fmaf(a.z, b.z, acc[2][2]); acc[2][3] = fmaf(a.z, b.w, acc[2][3]);
            acc[3][0] = fmaf(a.w, b.x, acc[3][0]); acc[3][1] = fmaf(a.w, b.y, acc[3][1]);
            acc[3][2] = fmaf(a.w, b.z, acc[3][2]); acc[3][3] = fmaf(a.w, b.w, acc[3][3]);
        }
        __syncthreads();
    }

    const int col = n0 + tx * 4;
    if (col < Nout) {
        float bx = bias[col], by = bias[col + 1], bz = bias[col + 2], bw = bias[col + 3];
        #pragma unroll
        for (int i = 0; i < 4; i++) {
            int row = m0 + ty * 4 + i;
            float4 v = make_float4(acc[i][0] + bx, acc[i][1] + by,
                                   acc[i][2] + bz, acc[i][3] + bw);
            if (doRelu) {
                v.x = fmaxf(v.x, 0.f); v.y = fmaxf(v.y, 0.f);
                v.z = fmaxf(v.z, 0.f); v.w = fmaxf(v.w, 0.f);
            }
            *(float4*)&C[(size_t)row * Nout + col] = v;
        }
    }
}

// ---------------- attention scores: warp per (node, head) --------------------
__global__ void attn_scores_kernel(const float* __restrict__ att_src,
                                   const float* __restrict__ att_dst) {
    int gw = (blockIdx.x * blockDim.x + threadIdx.x) >> 5;
    int lane = threadIdx.x & 31;
    if (gw >= N_NODES * HEADS) return;
    int node = gw >> 1, head = gw & 1;
    const float* hp = g_h + (size_t)node * F_DIM + head * OUT_CH + lane * 8;
    const float* sp = att_src + head * OUT_CH + lane * 8;
    const float* dp = att_dst + head * OUT_CH + lane * 8;
    float4 h0 = *(const float4*)hp,  h1 = *(const float4*)(hp + 4);
    float4 s0 = *(const float4*)sp,  s1 = *(const float4*)(sp + 4);
    float4 d0 = *(const float4*)dp,  d1 = *(const float4*)(dp + 4);
    float s = h0.x * s0.x + h0.y * s0.y + h0.z * s0.z + h0.w * s0.w
            + h1.x * s1.x + h1.y * s1.y + h1.z * s1.z + h1.w * s1.w;
    float d = h0.x * d0.x + h0.y * d0.y + h0.z * d0.z + h0.w * d0.w
            + h1.x * d1.x + h1.y * d1.y + h1.z * d1.z + h1.w * d1.w;
    #pragma unroll
    for (int o = 16; o; o >>= 1) {
        s += __shfl_xor_sync(0xffffffffu, s, o);
        d += __shfl_xor_sync(0xffffffffu, d, o);
    }
    if (lane == 0) { g_as[gw] = s; g_ad[gw] = d; }
}

// ---------------- fused GAT: softmax + aggregate + bias + relu + bf16 split --
__global__ __launch_bounds__(128)
void gat_agg_kernel(const float* __restrict__ conv_b) {
    const int dst = blockIdx.x;
    const int t = threadIdx.x;
    __shared__ float red[128];
    __shared__ float sh_a0[128], sh_a1[128];
    __shared__ int   sh_src[128];
    __shared__ float sm0, sm1, ss0, ss1;

    const int off = g_off[dst];
    const int deg = g_off[dst + 1] - off;
    const float ad0 = g_ad[dst * 2], ad1 = g_ad[dst * 2 + 1];
    const float self0 = lrelu(g_as[dst * 2] + ad0);
    const float self1 = lrelu(g_as[dst * 2 + 1] + ad1);

    float m0 = self0, m1 = self1;
    for (int j = t; j < deg; j += 128) {
        int s = g_csr_src[off + j];
        m0 = fmaxf(m0, lrelu(g_as[s * 2] + ad0));
        m1 = fmaxf(m1, lrelu(g_as[s * 2 + 1] + ad1));
    }
    red[t] = m0; __syncthreads();
    for (int d = 64; d; d >>= 1) { if (t < d) red[t] = fmaxf(red[t], red[t + d]); __syncthreads(); }
    if (t == 0) sm0 = red[0];
    __syncthreads();
    red[t] = m1; __syncthreads();
    for (int d = 64; d; d >>= 1) { if (t < d) red[t] = fmaxf(red[t], red[t + d]); __syncthreads(); }
    if (t == 0) sm1 = red[0];
    __syncthreads();
    m0 = sm0; m1 = sm1;

    float s0 = (t == 0) ? expf(self0 - m0) : 0.f;
    float s1 = (t == 0) ? expf(self1 - m1) : 0.f;
    for (int j = t; j < deg; j += 128) {
        int s = g_csr_src[off + j];
        s0 += expf(lrelu(g_as[s * 2] + ad0) - m0);
        s1 += expf(lrelu(g_as[s * 2 + 1] + ad1) - m1);
    }
    red[t] = s0; __syncthreads();
    for (int d = 64; d; d >>= 1) { if (t < d) red[t] += red[t + d]; __syncthreads(); }
    if (t == 0) ss0 = red[0];
    __syncthreads();
    red[t] = s1; __syncthreads();
    for (int d = 64; d; d >>= 1) { if (t < d) red[t] += red[t + d]; __syncthreads(); }
    if (t == 0) ss1 = red[0];
    __syncthreads();
    const float rs0 = 1.f / ss0, rs1 = 1.f / ss1;

    const int head = t >> 6;
    const float mself  = head ? self1 : self0;
    const float mmax   = head ? sm1 : sm0;
    const float rss    = head ? rs1 : rs0;
    const float a_self = expf(mself - mmax) * rss;

    float4 v = *(const float4*)&g_h[(size_t)dst * F_DIM + t * 4];
    float4 acc = make_float4(a_self * v.x, a_self * v.y, a_self * v.z, a_self * v.w);

    for (int c = 0; c < deg; c += 128) {
        int j = c + t;
        if (j < deg) {
            int s = g_csr_src[off + j];
            sh_src[t] = s;
            sh_a0[t] = expf(lrelu(g_as[s * 2] + ad0) - sm0) * rs0;
            sh_a1[t] = expf(lrelu(g_as[s * 2 + 1] + ad1) - sm1) * rs1;
        }
        __syncthreads();
        int cnt = min(128, deg - c);
        for (int j2 = 0; j2 < cnt; j2++) {
            const float4 hv = *(const float4*)&g_h[(size_t)sh_src[j2] * F_DIM + t * 4];
            float a = head ? sh_a1[j2] : sh_a0[j2];
            acc.x = fmaf(a, hv.x, acc.x);
            acc.y = fmaf(a, hv.y, acc.y);
            acc.z = fmaf(a, hv.z, acc.z);
            acc.w = fmaf(a, hv.w, acc.w);
        }
        __syncthreads();
    }

    float4 b = *(const float4*)&conv_b[t * 4];
    acc.x = fmaxf(acc.x + b.x, 0.f);
    acc.y = fmaxf(acc.y + b.y, 0.f);
    acc.z = fmaxf(acc.z + b.z, 0.f);
    acc.w = fmaxf(acc.w + b.w, 0.f);
    __nv_bfloat162 h0, l0, h1, l1;
    split2(acc.x, acc.y, h0, l0);
    split2(acc.z, acc.w, h1, l1);
    size_t idx = (size_t)dst * F_DIM + t * 4;
    *(__nv_bfloat162*)&g_ah[idx]     = h0;
    *(__nv_bfloat162*)&g_ah[idx + 2] = h1;
    *(__nv_bfloat162*)&g_al[idx]     = l0;
    *(__nv_bfloat162*)&g_al[idx + 2] = l1;
}

// ---------------- last MLP layer: 32 -> 3, also store |p|^2 -------------------
__global__ __launch_bounds__(256)
void final_layer_kernel(const float* __restrict__ W4, const float* __restrict__ b4) {
    __shared__ float w[3][32];
    __shared__ float bb[3];
    int tid = threadIdx.x;
    if (tid < 96) w[tid / 32][tid & 31] = W4[tid];
    if (tid < 3)  bb[tid] = b4[tid];
    __syncthreads();
    int n = blockIdx.x * blockDim.x + tid;
    if (n >= N_NODES) return;
    const float4* hp = (const float4*)(g_h4 + (size_t)n * 32);
    float a0 = bb[0], a1 = bb[1], a2 = bb[2];
    #pragma unroll
    for (int q = 0; q < 8; q++) {
        float4 v = hp[q];
        a0 = fmaf(v.x, w[0][q*4+0], a0); a0 = fmaf(v.y, w[0][q*4+1], a0);
        a0 = fmaf(v.z, w[0][q*4+2], a0); a0 = fmaf(v.w, w[0][q*4+3], a0);
        a1 = fmaf(v.x, w[1][q*4+0], a1); a1 = fmaf(v.y, w[1][q*4+1], a1);
        a1 = fmaf(v.z, w[1][q*4+2], a1); a1 = fmaf(v.w, w[1][q*4+3], a1);
        a2 = fmaf(v.x, w[2][q*4+0], a2); a2 = fmaf(v.y, w[2][q*4+1], a2);
        a2 = fmaf(v.z, w[2][q*4+2], a2); a2 = fmaf(v.w, w[2][q*4+3], a2);
    }
    float sq = fmaf(a0, a0, fmaf(a1, a1, a2 * a2));
    ((float4*)g_h5)[n] = make_float4(a0, a1, a2, sq);
}

// ---------------- pairwise distances: d2 = sp+sq-2*dot, MUFU rsqrt ------------
__global__ __launch_bounds__(256)
void cdist_kernel(float* __restrict__ out) {
    __shared__ float4 rp[128];
    __shared__ float4 cp[128];
    int tid = threadIdx.x;
    int rb = blockIdx.y * 128, cb = blockIdx.x * 128;
    if (tid < 128) rp[tid] = ((const float4*)g_h5)[rb + tid];
    else           cp[tid - 128] = ((const float4*)g_h5)[cb + tid - 128];
    __syncthreads();
    int tx = tid & 31, ty = tid >> 5;
    float4 q0 = cp[tx * 4 + 0], q1 = cp[tx * 4 + 1],
           q2 = cp[tx * 4 + 2], q3 = cp[tx * 4 + 3];
    #pragma unroll
    for (int j = 0; j < 16; j++) {
        int r = j * 8 + ty;
        float4 p = rp[r];
        float4 o;
        float t, d2;
        t = p.x * q0.x; t = fmaf(p.y, q0.y, t); t = fmaf(p.z, q0.z, t);
        d2 = fmaf(-2.f, t, p.w + q0.w); d2 = fmaxf(d2, 0.f);
        o.x = d2 * rsqrt_approx(fmaxf(d2, 1e-35f));
        t = p.x * q1.x; t = fmaf(p.y, q1.y, t); t = fmaf(p.z, q1.z, t);
        d2 = fmaf(-2.f, t, p.w + q1.w); d2 = fmaxf(d2, 0.f);
        o.y = d2 * rsqrt_approx(fmaxf(d2, 1e-35f));
        t = p.x * q2.x; t = fmaf(p.y, q2.y, t); t = fmaf(p.z, q2.z, t);
        d2 = fmaf(-2.f, t, p.w + q2.w); d2 = fmaxf(d2, 0.f);
        o.z = d2 * rsqrt_approx(fmaxf(d2, 1e-35f));
        t = p.x * q3.x; t = fmaf(p.y, q3.y, t); t = fmaf(p.z, q3.z, t);
        d2 = fmaf(-2.f, t, p.w + q3.w); d2 = fmaxf(d2, 0.f);
        o.w = d2 * rsqrt_approx(fmaxf(d2, 1e-35f));
        __stcs((float4*)&out[(size_t)(rb + r) * N_NODES + cb + tx * 4], o);
    }
}

// ---------------- launch -------------------------------------------------------
extern "C" void kernel_launch(void* const* d_in, const int* in_sizes, int n_in,
                              void* d_out, int out_size) {
    const float* x       = (const float*)d_in[0];
    const void*  ei      = (const void*)d_in[1];
    const float* conv_W  = (const float*)d_in[2];
    const float* att_src = (const float*)d_in[3];
    const float* att_dst = (const float*)d_in[4];
    const float* conv_b  = (const float*)d_in[5];
    const float* Wa = (const float*)d_in[6];  const float* ba = (const float*)d_in[7];
    const float* W1 = (const float*)d_in[8];  const float* b1 = (const float*)d_in[9];
    const float* W2 = (const float*)d_in[10]; const float* b2 = (const float*)d_in[11];
    const float* W3 = (const float*)d_in[12]; const float* b3 = (const float*)d_in[13];
    const float* W4 = (const float*)d_in[14]; const float* b4 = (const float*)d_in[15];
    float*       out = (float*)d_out;

    const int TCSMEM = NSTG * STGB;
    static bool init_done = false;
    static cudaStream_t s2;
    static cudaEvent_t evFork, evJoin;
    if (!init_done) {
        cudaFuncSetAttribute(gemm_tc_kernel,
                             cudaFuncAttributeMaxDynamicSharedMemorySize, TCSMEM);
        cudaStreamCreateWithFlags(&s2, cudaStreamNonBlocking);
        cudaEventCreateWithFlags(&evFork, cudaEventDisableTiming);
        cudaEventCreateWithFlags(&evJoin, cudaEventDisableTiming);
        init_done = true;
    }

    detect_idx_kernel<<<1, 32>>>(ei);
    cudaEventRecord(evFork, 0);
    cudaStreamWaitEvent(s2, evFork, 0);

    // side stream: weight splits + CSR build
    split_kernel<<<(F_DIM * IN_DIM / 4 + 255) / 256, 256, 0, s2>>>(conv_W, F_DIM * IN_DIM / 4, 1);
    split_kernel<<<(256 * 512 / 4 + 255) / 256, 256, 0, s2>>>(Wa, 256 * 512 / 4, 2);
    split_kernel<<<(128 * 256 / 4 + 255) / 256, 256, 0, s2>>>(W1, 128 * 256 / 4, 3);
    zero_deg_kernel<<<(N_NODES + 255) / 256, 256, 0, s2>>>();
    hist_kernel<<<(E_IN + 255) / 256, 256, 0, s2>>>(ei);
    scan_kernel<<<1, 1024, 0, s2>>>();
    scatter_kernel<<<(E_IN + 255) / 256, 256, 0, s2>>>(ei);
    cudaEventRecord(evJoin, s2);

    // main stream: activation split
    split_kernel<<<(N_NODES * IN_DIM / 4 + 255) / 256, 256>>>(x, N_NODES * IN_DIM / 4, 0);
    cudaStreamWaitEvent(0, evJoin, 0);

    gemm_tc_kernel<<<dim3(F_DIM / 128, N_NODES / 128), 256, TCSMEM>>>(
        nullptr, BUF_H, F_DIM, IN_DIM, 0, 0, 0, 0);

    attn_scores_kernel<<<(N_NODES * HEADS * 32 + 255) / 256, 256>>>(att_src, att_dst);
    gat_agg_kernel<<<N_NODES, 128>>>(conv_b);

    gemm_tc_kernel<<<dim3(256 / 128, N_NODES / 128), 256, TCSMEM>>>(
        ba, BUF_H, 256, 512, 1, 0, 1, 1);

    gemm_tc_kernel<<<dim3(128 / 128, N_NODES / 128), 256, TCSMEM>>>(
        b1, BUF_H2, 128, 256, 1, 1, 0, 2);

    gemm_kernel<<<dim3(1, N_NODES / 64), 256>>>(BUF_H2, W2, b2, BUF_H3, 64, 128, 1);
    gemm_kernel<<<dim3(1, N_NODES / 64), 256>>>(BUF_H3, W3, b3, BUF_H4, 32, 64, 1);
    final_layer_kernel<<<N_NODES / 256, 256>>>(W4, b4);

    cdist_kernel<<<dim3(N_NODES / 128, N_NODES / 128), 256>>>(out);
}